// round 13
// baseline (speedup 1.0000x reference)
#include <cuda_runtime.h>
#include <math.h>
#include <stdint.h>

#define T_INc  128
#define T_OUTc 12
#define LAT    256
#define SQ     140
#define BB     256
#define NROWS  (SQ*BB)      // 35840
#define RBLK   280          // 35840/128

__device__ float g_enc[SQ*BB*LAT];
__device__ float g_gi [T_INc*BB*3*LAT];
__device__ float g_Q  [T_OUTc*BB*LAT];
__device__ float g_h  [BB*LAT];
__device__ float g_pm [T_OUTc*RBLK*BB];
__device__ float g_ps [T_OUTc*RBLK*BB];
__device__ int   g_pidx[T_OUTc*RBLK*BB];
__device__ float g_diag[T_OUTc*BB];
__device__ float g_dll [T_OUTc*BB];
__device__ int   g_corr[T_OUTc*BB];

typedef unsigned long long u64;

#define FMA2(d, a, b) \
    asm("fma.rn.f32x2 %0, %1, %2, %0;" : "+l"(d) : "l"(a), "l"(b))
#define PACK2(out, lo, hi) \
    asm("mov.b64 %0, {%1, %2};" : "=l"(out) : "f"(lo), "f"(hi))
#define UNPACK2(lo, hi, in) \
    asm("mov.b64 {%0, %1}, %2;" : "=f"(lo), "=f"(hi) : "l"(in))

__device__ __forceinline__ float to_tf32(float x) {
    float y;
    asm("cvt.rna.tf32.f32 %0, %1;" : "=f"(y) : "f"(x));
    return y;
}

__device__ __forceinline__ void mma_tf32(float d[4],
                                         const uint32_t a[4],
                                         const uint32_t b[2]) {
    asm volatile(
        "mma.sync.aligned.m16n8k8.row.col.f32.tf32.tf32.f32 "
        "{%0,%1,%2,%3}, {%4,%5,%6,%7}, {%8,%9}, {%0,%1,%2,%3};"
        : "+f"(d[0]), "+f"(d[1]), "+f"(d[2]), "+f"(d[3])
        : "r"(a[0]), "r"(a[1]), "r"(a[2]), "r"(a[3]),
          "r"(b[0]), "r"(b[1]));
}

// ---------------------------------------------------------------- conv
__global__ void conv_kernel(const float* __restrict__ X,
                            const float* __restrict__ W,
                            const float* __restrict__ bias) {
    __shared__ float Xs[960];
    const int b = blockIdx.y, t0 = blockIdx.x*20, o = threadIdx.x;
    float w[48];
#pragma unroll
    for (int i = 0; i < 48; i++) w[i] = W[o*48+i];
    const float bb = bias[o];
    const float* xp = X + ((long)b*2048 + (long)t0*4)*12;
    for (int i = threadIdx.x; i < 960; i += 256) Xs[i] = xp[i];
    __syncthreads();
    for (int tt = 0; tt < 20; tt++) {
        float acc = bb;
#pragma unroll
        for (int s = 0; s < 4; s++)
#pragma unroll
            for (int c = 0; c < 12; c++)
                acc += Xs[(tt*4+s)*12+c] * w[c*4+s];
        g_enc[((long)(t0+tt)*BB + b)*LAT + o] = acc;
    }
}

// ------------------------------------------------- packed-f32x2 fp32 GEMM (GI, Q)
__device__ __forceinline__ void gemm_tile2(const float* __restrict__ A,
                                           const float* __restrict__ Bm,
                                           int m0, int n0,
                                           u64 acc2[8][4],
                                           float As[16][128], float Bs[16][128]) {
    const int tid = threadIdx.x, tx = tid & 15, ty = tid >> 4;
#pragma unroll
    for (int r = 0; r < 8; r++)
#pragma unroll
        for (int p = 0; p < 4; p++) acc2[r][p] = 0ull;
    for (int kt = 0; kt < 256; kt += 16) {
#pragma unroll
        for (int i = 0; i < 2; i++) {
            int v = tid*2+i, row = v>>2, kk = (v&3)*4;
            float4 a = *(const float4*)(A + (long)(m0+row)*256 + kt + kk);
            As[kk+0][row]=a.x; As[kk+1][row]=a.y; As[kk+2][row]=a.z; As[kk+3][row]=a.w;
            float4 bq = *(const float4*)(Bm + (long)(n0+row)*256 + kt + kk);
            Bs[kk+0][row]=bq.x; Bs[kk+1][row]=bq.y; Bs[kk+2][row]=bq.z; Bs[kk+3][row]=bq.w;
        }
        __syncthreads();
#pragma unroll
        for (int kk = 0; kk < 16; kk++) {
            float a[8];
            *(float4*)(a)   = *(const float4*)&As[kk][ty*4];
            *(float4*)(a+4) = *(const float4*)&As[kk][64+ty*4];
            float4 b0 = *(const float4*)&Bs[kk][tx*4];
            float4 b1 = *(const float4*)&Bs[kk][64+tx*4];
            u64 bp[4];
            PACK2(bp[0], b0.x, b0.y); PACK2(bp[1], b0.z, b0.w);
            PACK2(bp[2], b1.x, b1.y); PACK2(bp[3], b1.z, b1.w);
#pragma unroll
            for (int r = 0; r < 8; r++) {
                u64 av; PACK2(av, a[r], a[r]);
#pragma unroll
                for (int p = 0; p < 4; p++) FMA2(acc2[r][p], av, bp[p]);
            }
        }
        __syncthreads();
    }
}

__device__ __forceinline__ void unpack_acc(const u64 acc2[8][4], float acc[8][8]) {
#pragma unroll
    for (int r = 0; r < 8; r++) {
        UNPACK2(acc[r][0], acc[r][1], acc2[r][0]);
        UNPACK2(acc[r][2], acc[r][3], acc2[r][1]);
        UNPACK2(acc[r][4], acc[r][5], acc2[r][2]);
        UNPACK2(acc[r][6], acc[r][7], acc2[r][3]);
    }
}

__global__ void gemm_bias_kernel(const float* __restrict__ A,
                                 const float* __restrict__ Bm,
                                 const float* __restrict__ bias,
                                 float* __restrict__ C,
                                 int ldA_batch, int ldB_batch, int ldbias_batch,
                                 int ldC_batch, int ncols) {
    __shared__ float As[16][128], Bs[16][128];
    u64 acc2[8][4];
    float acc[8][8];
    const int k = blockIdx.z;
    const int m0 = blockIdx.x*128, n0 = blockIdx.y*128;
    gemm_tile2(A + (long)k*ldA_batch, Bm + (long)k*ldB_batch, m0, n0, acc2, As, Bs);
    unpack_acc(acc2, acc);
    const float* bk = bias + (long)k*ldbias_batch;
    float* Ck = C + (long)k*ldC_batch;
    const int tx = threadIdx.x & 15, ty = threadIdx.x >> 4;
#pragma unroll
    for (int r = 0; r < 8; r++) {
        int grow = m0 + ((r<4) ? ty*4+r : 64+ty*4+(r-4));
#pragma unroll
        for (int h = 0; h < 2; h++) {
            int gc = n0 + (h?64:0) + tx*4;
            float4 v;
            v.x = acc[r][h*4+0]+bk[gc+0]; v.y = acc[r][h*4+1]+bk[gc+1];
            v.z = acc[r][h*4+2]+bk[gc+2]; v.w = acc[r][h*4+3]+bk[gc+3];
            *(float4*)(Ck + (long)grow*ncols + gc) = v;
        }
    }
}

// ---------------------------------------------------------------- GRU (64 CTAs x 4 chains)
__global__ void gru_kernel(const float* __restrict__ Whh,
                           const float* __restrict__ bhh,
                           float* __restrict__ out) {
    __shared__ float h_s[4][256];
    __shared__ float part[3][4][256];
    const int tid = threadIdx.x, hid = tid & 255, ks = tid >> 8;
    const int b0 = blockIdx.x * 4;
    for (int i = tid; i < 1024; i += 512) ((float*)h_s)[i] = 0.f;
    float bh0=0.f, bh1=0.f, bh2=0.f;
    if (ks == 0) { bh0 = bhh[hid]; bh1 = bhh[256+hid]; bh2 = bhh[512+hid]; }
    __syncthreads();
    const float* W0 = Whh + (long)hid*256;
    const float* W1 = Whh + (long)(256+hid)*256;
    const float* W2 = Whh + (long)(512+hid)*256;
    const int kbase = ks * 128;
    for (int t = 0; t < T_INc; t++) {
        float a0[4]={0,0,0,0}, a1[4]={0,0,0,0}, a2[4]={0,0,0,0};
#pragma unroll 4
        for (int k = kbase; k < kbase+128; k += 4) {
            float4 w0 = *(const float4*)(W0+k);
            float4 w1 = *(const float4*)(W1+k);
            float4 w2 = *(const float4*)(W2+k);
#pragma unroll
            for (int bl = 0; bl < 4; bl++) {
                float4 hv = *(const float4*)&h_s[bl][k];
                a0[bl] += w0.x*hv.x + w0.y*hv.y + w0.z*hv.z + w0.w*hv.w;
                a1[bl] += w1.x*hv.x + w1.y*hv.y + w1.z*hv.z + w1.w*hv.w;
                a2[bl] += w2.x*hv.x + w2.y*hv.y + w2.z*hv.z + w2.w*hv.w;
            }
        }
        if (ks == 1) {
#pragma unroll
            for (int bl = 0; bl < 4; bl++) {
                part[0][bl][hid]=a0[bl]; part[1][bl][hid]=a1[bl]; part[2][bl][hid]=a2[bl];
            }
        }
        __syncthreads();
        if (ks == 0) {
            const float* gi = g_gi + ((long)t*BB + b0)*768;
#pragma unroll
            for (int bl = 0; bl < 4; bl++) {
                float ghr = a0[bl]+part[0][bl][hid]+bh0;
                float ghz = a1[bl]+part[1][bl][hid]+bh1;
                float ghn = a2[bl]+part[2][bl][hid]+bh2;
                float gr = gi[(long)bl*768 + hid]     + ghr;
                float gz = gi[(long)bl*768 + 256+hid] + ghz;
                float gn = gi[(long)bl*768 + 512+hid];
                float r = 1.f/(1.f+expf(-gr));
                float z = 1.f/(1.f+expf(-gz));
                float n = tanhf(gn + r*ghn);
                h_s[bl][hid] = (1.f-z)*n + z*h_s[bl][hid];
            }
        }
        __syncthreads();
    }
    if (ks == 0) {
#pragma unroll
        for (int bl = 0; bl < 4; bl++) {
            int b = b0+bl;
            float hv = h_s[bl][hid];
            g_h[b*256+hid] = hv;
            out[2 + b*256 + hid] = hv;
        }
    }
}

// --------------------------------------- sim: tf32 mma, vectorized fragments (R7)
__global__ void __launch_bounds__(256) sim_mma_kernel() {
    extern __shared__ float dsm[];
    float* Asf = dsm;                 // [128*16]
    float* Bsf = dsm + 2048;          // [128*16]
    float* slab = dsm;                // [128][130] epilogue, reuses staging

    __shared__ float redm[2][128], reds[2][128], colmax_s[128];
    __shared__ int   redi[2][128];

    const int tid = threadIdx.x, lane = tid & 31, warp = tid >> 5;
    const int wm = (warp & 3) * 32;
    const int wn = (warp >> 2) * 64;
    const int lq = lane & 3, lr = lane >> 2;
    const int rb = blockIdx.x, cb = blockIdx.y, k = blockIdx.z;
    const int m0 = rb*128, n0 = cb*128;
    const float* Ag = g_enc + (size_t)m0*256;
    const float* Bg = g_Q + (size_t)k*BB*LAT + (size_t)n0*256;

    float acc[2][8][4];
#pragma unroll
    for (int mt = 0; mt < 2; mt++)
#pragma unroll
        for (int nt = 0; nt < 8; nt++)
#pragma unroll
            for (int i = 0; i < 4; i++) acc[mt][nt][i] = 0.f;

    for (int kt = 0; kt < 256; kt += 16) {
#pragma unroll
        for (int s = 0; s < 2; s++) {
            int v = tid*2 + s;
            int m = v >> 2, j = v & 3;
            float4 av = *(const float4*)(Ag + (size_t)m*256 + kt + j*4);
            av.x = to_tf32(av.x); av.y = to_tf32(av.y);
            av.z = to_tf32(av.z); av.w = to_tf32(av.w);
            *(float4*)(Asf + m*16 + j*4) = av;
            float4 bv = *(const float4*)(Bg + (size_t)m*256 + kt + j*4);
            bv.x = to_tf32(bv.x); bv.y = to_tf32(bv.y);
            bv.z = to_tf32(bv.z); bv.w = to_tf32(bv.w);
            *(float4*)(Bsf + m*16 + j*4) = bv;
        }
        __syncthreads();

        float4 alo[2], ahi[2];
#pragma unroll
        for (int mt = 0; mt < 2; mt++) {
            int mrow = wm + mt*16 + lr;
            alo[mt] = *(const float4*)(Asf + mrow*16 + lq*4);
            ahi[mt] = *(const float4*)(Asf + (mrow+8)*16 + lq*4);
        }
#pragma unroll
        for (int nt = 0; nt < 8; nt++) {
            int nrow = wn + nt*8 + lr;
            float4 bv = *(const float4*)(Bsf + nrow*16 + lq*4);
            uint32_t b0[2] = { __float_as_uint(bv.x), __float_as_uint(bv.y) };
            uint32_t b1[2] = { __float_as_uint(bv.z), __float_as_uint(bv.w) };
#pragma unroll
            for (int mt = 0; mt < 2; mt++) {
                uint32_t a0[4] = { __float_as_uint(alo[mt].x), __float_as_uint(ahi[mt].x),
                                   __float_as_uint(alo[mt].y), __float_as_uint(ahi[mt].y) };
                mma_tf32(acc[mt][nt], a0, b0);
                uint32_t a1[4] = { __float_as_uint(alo[mt].z), __float_as_uint(ahi[mt].z),
                                   __float_as_uint(alo[mt].w), __float_as_uint(ahi[mt].w) };
                mma_tf32(acc[mt][nt], a1, b1);
            }
        }
        __syncthreads();
    }

    // store accums to slab [128][130]
#pragma unroll
    for (int mt = 0; mt < 2; mt++) {
        int r = wm + mt*16 + lr;
#pragma unroll
        for (int nt = 0; nt < 8; nt++) {
            int c = wn + nt*8 + lq*2;
            *(float2*)(slab + (size_t)r*130 + c)     = make_float2(acc[mt][nt][0], acc[mt][nt][1]);
            *(float2*)(slab + (size_t)(r+8)*130 + c) = make_float2(acc[mt][nt][2], acc[mt][nt][3]);
        }
    }
    __syncthreads();

    const int col = tid & 127, seg = tid >> 7;
    {
        float m = -INFINITY; int ri = 0;
        for (int r = seg*64; r < seg*64 + 64; r++) {
            float v = slab[(size_t)r*130 + col];
            if (v > m) { m = v; ri = r; }
        }
        redm[seg][col] = m; redi[seg][col] = ri;
    }
    __syncthreads();
    if (tid < 128) {
        float m = redm[0][tid]; int ri = redi[0][tid];
        float v = redm[1][tid];
        if (v > m) { m = v; ri = redi[1][tid]; }
        colmax_s[tid] = m;
        long pi = ((long)k*RBLK + rb)*BB + n0 + tid;
        g_pm[pi] = m; g_pidx[pi] = m0 + ri;
        int tr = (T_INc + k)*BB + n0 + tid - m0;
        if (tr >= 0 && tr < 128)
            g_diag[k*BB + n0 + tid] = slab[(size_t)tr*130 + tid];
    }
    __syncthreads();
    {
        float cm = colmax_s[col], s = 0.f;
        for (int r = seg*64; r < seg*64 + 64; r++)
            s += expf(slab[(size_t)r*130 + col] - cm);
        reds[seg][col] = s;
    }
    __syncthreads();
    if (tid < 128) {
        long pi = ((long)k*RBLK + rb)*BB + n0 + tid;
        g_ps[pi] = reds[0][tid] + reds[1][tid];
    }
}

// ---------------------------------------------------------------- combine / finalize
__global__ void combine_kernel() {
    const int k = blockIdx.x, c = threadIdx.x;
    const float* pm = g_pm + (long)k*RBLK*BB;
    const int*  pid = g_pidx + (long)k*RBLK*BB;
    const float* ps = g_ps + (long)k*RBLK*BB;
    float m = pm[c]; int idx = pid[c];
    for (int rb = 1; rb < RBLK; rb++) {
        float v = pm[(long)rb*BB + c];
        if (v > m) { m = v; idx = pid[(long)rb*BB + c]; }
    }
    float s = 0.f;
    for (int rb = 0; rb < RBLK; rb++)
        s += ps[(long)rb*BB + c] * expf(pm[(long)rb*BB + c] - m);
    float lse = m + logf(s);
    g_dll[k*BB + c] = g_diag[k*BB + c] - lse;
    g_corr[k*BB + c] = (idx == BB*(T_INc + k) + c) ? 1 : 0;
}

__global__ void finalize_kernel(float* __restrict__ out) {
    __shared__ float ssum[256];
    __shared__ int scnt[256];
    const int tid = threadIdx.x;
    float s = 0.f; int cnt = 0;
    for (int i = tid; i < T_OUTc*BB; i += 256) { s += g_dll[i]; cnt += g_corr[i]; }
    ssum[tid] = s; scnt[tid] = cnt;
    __syncthreads();
    for (int o = 128; o > 0; o >>= 1) {
        if (tid < o) { ssum[tid] += ssum[tid+o]; scnt[tid] += scnt[tid+o]; }
        __syncthreads();
    }
    if (tid == 0) {
        out[0] = (float)scnt[0] / (float)(T_OUTc*BB);
        out[1] = -ssum[0] / (float)(T_OUTc*BB);
    }
}

extern "C" void kernel_launch(void* const* d_in, const int* in_sizes, int n_in,
                              void* d_out, int out_size) {
    const float* X      = (const float*)d_in[0];
    const float* conv_w = (const float*)d_in[1];
    const float* conv_b = (const float*)d_in[2];
    const float* W_ih   = (const float*)d_in[3];
    const float* W_hh   = (const float*)d_in[4];
    const float* b_ih   = (const float*)d_in[5];
    const float* b_hh   = (const float*)d_in[6];
    const float* pred_W = (const float*)d_in[7];
    const float* pred_b = (const float*)d_in[8];
    float* out = (float*)d_out;

    float* enc_p; cudaGetSymbolAddress((void**)&enc_p, g_enc);
    float* gi_p;  cudaGetSymbolAddress((void**)&gi_p,  g_gi);
    float* h_p;   cudaGetSymbolAddress((void**)&h_p,   g_h);
    float* Q_p;   cudaGetSymbolAddress((void**)&Q_p,   g_Q);

    const int SIM_SMEM = 128*130*4;   // 66560 B (slab ⊇ 16KB staging)
    cudaFuncSetAttribute(sim_mma_kernel,
                         cudaFuncAttributeMaxDynamicSharedMemorySize, SIM_SMEM);

    conv_kernel<<<dim3(7,256), 256>>>(X, conv_w, conv_b);
    gemm_bias_kernel<<<dim3(256,6,1), 256>>>(enc_p, W_ih, b_ih, gi_p, 0,0,0,0, 768);
    gru_kernel<<<64, 512>>>(W_hh, b_hh, out);
    gemm_bias_kernel<<<dim3(2,2,12), 256>>>(h_p, pred_W, pred_b, Q_p,
                                            0, LAT*LAT, LAT, BB*LAT, LAT);
    sim_mma_kernel<<<dim3(RBLK, 2, T_OUTc), 256, SIM_SMEM>>>();
    combine_kernel<<<T_OUTc, 256>>>();
    finalize_kernel<<<1, 256>>>(out);
}

// round 14
// speedup vs baseline: 1.0580x; 1.0580x over previous
#include <cuda_runtime.h>
#include <math.h>
#include <stdint.h>

#define T_INc  128
#define T_OUTc 12
#define LAT    256
#define SQ     140
#define BB     256
#define NROWS  (SQ*BB)      // 35840
#define RBLK   280          // 35840/128

__device__ float g_enc[SQ*BB*LAT];
__device__ float g_gi [T_INc*BB*3*LAT];
__device__ float g_Q  [T_OUTc*BB*LAT];
__device__ float g_h  [BB*LAT];
__device__ float g_pm [T_OUTc*RBLK*BB];
__device__ float g_ps [T_OUTc*RBLK*BB];
__device__ int   g_pidx[T_OUTc*RBLK*BB];
__device__ float g_diag[T_OUTc*BB];
__device__ float g_dll [T_OUTc*BB];
__device__ int   g_corr[T_OUTc*BB];

typedef unsigned long long u64;

#define FMA2(d, a, b) \
    asm("fma.rn.f32x2 %0, %1, %2, %0;" : "+l"(d) : "l"(a), "l"(b))
#define PACK2(out, lo, hi) \
    asm("mov.b64 %0, {%1, %2};" : "=l"(out) : "f"(lo), "f"(hi))
#define UNPACK2(lo, hi, in) \
    asm("mov.b64 {%0, %1}, %2;" : "=f"(lo), "=f"(hi) : "l"(in))

__device__ __forceinline__ float to_tf32(float x) {
    float y;
    asm("cvt.rna.tf32.f32 %0, %1;" : "=f"(y) : "f"(x));
    return y;
}

__device__ __forceinline__ void mma_tf32(float d[4],
                                         const uint32_t a[4],
                                         const uint32_t b[2]) {
    asm volatile(
        "mma.sync.aligned.m16n8k8.row.col.f32.tf32.tf32.f32 "
        "{%0,%1,%2,%3}, {%4,%5,%6,%7}, {%8,%9}, {%0,%1,%2,%3};"
        : "+f"(d[0]), "+f"(d[1]), "+f"(d[2]), "+f"(d[3])
        : "r"(a[0]), "r"(a[1]), "r"(a[2]), "r"(a[3]),
          "r"(b[0]), "r"(b[1]));
}

// MUFU-free exp for x <= 0 (clamped at -80): exp2 via bit trick + deg-5 Taylor.
// rel err ~2.4e-6 on the poly; exact at x=0 path within 1 ulp-ish.
__device__ __forceinline__ float fexp(float x) {
    x = fmaxf(x, -80.f);
    float y = x * 1.4426950408889634f;       // log2(e)
    float r = rintf(y);
    float f = y - r;
    float p = 1.3333558e-3f;
    p = fmaf(p, f, 9.6181291e-3f);
    p = fmaf(p, f, 5.5504110e-2f);
    p = fmaf(p, f, 2.4022651e-1f);
    p = fmaf(p, f, 6.9314718e-1f);
    p = fmaf(p, f, 1.0f);
    int i = (int)r;
    return __uint_as_float(__float_as_uint(p) + ((uint32_t)i << 23));
}

// ---------------------------------------------------------------- conv
__global__ void conv_kernel(const float* __restrict__ X,
                            const float* __restrict__ W,
                            const float* __restrict__ bias) {
    __shared__ float Xs[960];
    const int b = blockIdx.y, t0 = blockIdx.x*20, o = threadIdx.x;
    float w[48];
#pragma unroll
    for (int i = 0; i < 48; i++) w[i] = W[o*48+i];
    const float bb = bias[o];
    const float* xp = X + ((long)b*2048 + (long)t0*4)*12;
    for (int i = threadIdx.x; i < 960; i += 256) Xs[i] = xp[i];
    __syncthreads();
    for (int tt = 0; tt < 20; tt++) {
        float acc = bb;
#pragma unroll
        for (int s = 0; s < 4; s++)
#pragma unroll
            for (int c = 0; c < 12; c++)
                acc += Xs[(tt*4+s)*12+c] * w[c*4+s];
        g_enc[((long)(t0+tt)*BB + b)*LAT + o] = acc;
    }
}

// ------------------------------------------------- packed-f32x2 fp32 GEMM (GI, Q)
__device__ __forceinline__ void gemm_tile2(const float* __restrict__ A,
                                           const float* __restrict__ Bm,
                                           int m0, int n0,
                                           u64 acc2[8][4],
                                           float As[16][128], float Bs[16][128]) {
    const int tid = threadIdx.x, tx = tid & 15, ty = tid >> 4;
#pragma unroll
    for (int r = 0; r < 8; r++)
#pragma unroll
        for (int p = 0; p < 4; p++) acc2[r][p] = 0ull;
    for (int kt = 0; kt < 256; kt += 16) {
#pragma unroll
        for (int i = 0; i < 2; i++) {
            int v = tid*2+i, row = v>>2, kk = (v&3)*4;
            float4 a = *(const float4*)(A + (long)(m0+row)*256 + kt + kk);
            As[kk+0][row]=a.x; As[kk+1][row]=a.y; As[kk+2][row]=a.z; As[kk+3][row]=a.w;
            float4 bq = *(const float4*)(Bm + (long)(n0+row)*256 + kt + kk);
            Bs[kk+0][row]=bq.x; Bs[kk+1][row]=bq.y; Bs[kk+2][row]=bq.z; Bs[kk+3][row]=bq.w;
        }
        __syncthreads();
#pragma unroll
        for (int kk = 0; kk < 16; kk++) {
            float a[8];
            *(float4*)(a)   = *(const float4*)&As[kk][ty*4];
            *(float4*)(a+4) = *(const float4*)&As[kk][64+ty*4];
            float4 b0 = *(const float4*)&Bs[kk][tx*4];
            float4 b1 = *(const float4*)&Bs[kk][64+tx*4];
            u64 bp[4];
            PACK2(bp[0], b0.x, b0.y); PACK2(bp[1], b0.z, b0.w);
            PACK2(bp[2], b1.x, b1.y); PACK2(bp[3], b1.z, b1.w);
#pragma unroll
            for (int r = 0; r < 8; r++) {
                u64 av; PACK2(av, a[r], a[r]);
#pragma unroll
                for (int p = 0; p < 4; p++) FMA2(acc2[r][p], av, bp[p]);
            }
        }
        __syncthreads();
    }
}

__device__ __forceinline__ void unpack_acc(const u64 acc2[8][4], float acc[8][8]) {
#pragma unroll
    for (int r = 0; r < 8; r++) {
        UNPACK2(acc[r][0], acc[r][1], acc2[r][0]);
        UNPACK2(acc[r][2], acc[r][3], acc2[r][1]);
        UNPACK2(acc[r][4], acc[r][5], acc2[r][2]);
        UNPACK2(acc[r][6], acc[r][7], acc2[r][3]);
    }
}

__global__ void gemm_bias_kernel(const float* __restrict__ A,
                                 const float* __restrict__ Bm,
                                 const float* __restrict__ bias,
                                 float* __restrict__ C,
                                 int ldA_batch, int ldB_batch, int ldbias_batch,
                                 int ldC_batch, int ncols) {
    __shared__ float As[16][128], Bs[16][128];
    u64 acc2[8][4];
    float acc[8][8];
    const int k = blockIdx.z;
    const int m0 = blockIdx.x*128, n0 = blockIdx.y*128;
    gemm_tile2(A + (long)k*ldA_batch, Bm + (long)k*ldB_batch, m0, n0, acc2, As, Bs);
    unpack_acc(acc2, acc);
    const float* bk = bias + (long)k*ldbias_batch;
    float* Ck = C + (long)k*ldC_batch;
    const int tx = threadIdx.x & 15, ty = threadIdx.x >> 4;
#pragma unroll
    for (int r = 0; r < 8; r++) {
        int grow = m0 + ((r<4) ? ty*4+r : 64+ty*4+(r-4));
#pragma unroll
        for (int h = 0; h < 2; h++) {
            int gc = n0 + (h?64:0) + tx*4;
            float4 v;
            v.x = acc[r][h*4+0]+bk[gc+0]; v.y = acc[r][h*4+1]+bk[gc+1];
            v.z = acc[r][h*4+2]+bk[gc+2]; v.w = acc[r][h*4+3]+bk[gc+3];
            *(float4*)(Ck + (long)grow*ncols + gc) = v;
        }
    }
}

// ---------------------------------------------------------------- GRU (128 CTAs x 2 chains)
__global__ void gru_kernel(const float* __restrict__ Whh,
                           const float* __restrict__ bhh,
                           float* __restrict__ out) {
    __shared__ float h_s[2][256];
    __shared__ float part[3][2][256];
    const int tid = threadIdx.x, hid = tid & 255, ks = tid >> 8;
    const int b0 = blockIdx.x * 2;
    for (int i = tid; i < 512; i += 512) ((float*)h_s)[i] = 0.f;
    float bh0=0.f, bh1=0.f, bh2=0.f;
    if (ks == 0) { bh0 = bhh[hid]; bh1 = bhh[256+hid]; bh2 = bhh[512+hid]; }
    __syncthreads();
    const float* W0 = Whh + (long)hid*256;
    const float* W1 = Whh + (long)(256+hid)*256;
    const float* W2 = Whh + (long)(512+hid)*256;
    const int kbase = ks * 128;
    for (int t = 0; t < T_INc; t++) {
        float a0[2]={0,0}, a1[2]={0,0}, a2[2]={0,0};
#pragma unroll 4
        for (int k = kbase; k < kbase+128; k += 4) {
            float4 w0 = *(const float4*)(W0+k);
            float4 w1 = *(const float4*)(W1+k);
            float4 w2 = *(const float4*)(W2+k);
#pragma unroll
            for (int bl = 0; bl < 2; bl++) {
                float4 hv = *(const float4*)&h_s[bl][k];
                a0[bl] += w0.x*hv.x + w0.y*hv.y + w0.z*hv.z + w0.w*hv.w;
                a1[bl] += w1.x*hv.x + w1.y*hv.y + w1.z*hv.z + w1.w*hv.w;
                a2[bl] += w2.x*hv.x + w2.y*hv.y + w2.z*hv.z + w2.w*hv.w;
            }
        }
        if (ks == 1) {
#pragma unroll
            for (int bl = 0; bl < 2; bl++) {
                part[0][bl][hid]=a0[bl]; part[1][bl][hid]=a1[bl]; part[2][bl][hid]=a2[bl];
            }
        }
        __syncthreads();
        if (ks == 0) {
            const float* gi = g_gi + ((long)t*BB + b0)*768;
#pragma unroll
            for (int bl = 0; bl < 2; bl++) {
                float ghr = a0[bl]+part[0][bl][hid]+bh0;
                float ghz = a1[bl]+part[1][bl][hid]+bh1;
                float ghn = a2[bl]+part[2][bl][hid]+bh2;
                float gr = gi[(long)bl*768 + hid]     + ghr;
                float gz = gi[(long)bl*768 + 256+hid] + ghz;
                float gn = gi[(long)bl*768 + 512+hid];
                float r = 1.f/(1.f+expf(-gr));
                float z = 1.f/(1.f+expf(-gz));
                float n = tanhf(gn + r*ghn);
                h_s[bl][hid] = (1.f-z)*n + z*h_s[bl][hid];
            }
        }
        __syncthreads();
    }
    if (ks == 0) {
#pragma unroll
        for (int bl = 0; bl < 2; bl++) {
            int b = b0+bl;
            float hv = h_s[bl][hid];
            g_h[b*256+hid] = hv;
            out[2 + b*256 + hid] = hv;
        }
    }
}

// --------------------------------------- sim: tf32 mma, vectorized fragments (R7)
__global__ void __launch_bounds__(256) sim_mma_kernel() {
    extern __shared__ float dsm[];
    float* Asf = dsm;                 // [128*16]
    float* Bsf = dsm + 2048;          // [128*16]
    float* slab = dsm;                // [128][130] epilogue, reuses staging

    __shared__ float redm[2][128], reds[2][128], colmax_s[128];
    __shared__ int   redi[2][128];

    const int tid = threadIdx.x, lane = tid & 31, warp = tid >> 5;
    const int wm = (warp & 3) * 32;
    const int wn = (warp >> 2) * 64;
    const int lq = lane & 3, lr = lane >> 2;
    const int rb = blockIdx.x, cb = blockIdx.y, k = blockIdx.z;
    const int m0 = rb*128, n0 = cb*128;
    const float* Ag = g_enc + (size_t)m0*256;
    const float* Bg = g_Q + (size_t)k*BB*LAT + (size_t)n0*256;

    float acc[2][8][4];
#pragma unroll
    for (int mt = 0; mt < 2; mt++)
#pragma unroll
        for (int nt = 0; nt < 8; nt++)
#pragma unroll
            for (int i = 0; i < 4; i++) acc[mt][nt][i] = 0.f;

    for (int kt = 0; kt < 256; kt += 16) {
#pragma unroll
        for (int s = 0; s < 2; s++) {
            int v = tid*2 + s;
            int m = v >> 2, j = v & 3;
            float4 av = *(const float4*)(Ag + (size_t)m*256 + kt + j*4);
            av.x = to_tf32(av.x); av.y = to_tf32(av.y);
            av.z = to_tf32(av.z); av.w = to_tf32(av.w);
            *(float4*)(Asf + m*16 + j*4) = av;
            float4 bv = *(const float4*)(Bg + (size_t)m*256 + kt + j*4);
            bv.x = to_tf32(bv.x); bv.y = to_tf32(bv.y);
            bv.z = to_tf32(bv.z); bv.w = to_tf32(bv.w);
            *(float4*)(Bsf + m*16 + j*4) = bv;
        }
        __syncthreads();

        float4 alo[2], ahi[2];
#pragma unroll
        for (int mt = 0; mt < 2; mt++) {
            int mrow = wm + mt*16 + lr;
            alo[mt] = *(const float4*)(Asf + mrow*16 + lq*4);
            ahi[mt] = *(const float4*)(Asf + (mrow+8)*16 + lq*4);
        }
#pragma unroll
        for (int nt = 0; nt < 8; nt++) {
            int nrow = wn + nt*8 + lr;
            float4 bv = *(const float4*)(Bsf + nrow*16 + lq*4);
            uint32_t b0[2] = { __float_as_uint(bv.x), __float_as_uint(bv.y) };
            uint32_t b1[2] = { __float_as_uint(bv.z), __float_as_uint(bv.w) };
#pragma unroll
            for (int mt = 0; mt < 2; mt++) {
                uint32_t a0[4] = { __float_as_uint(alo[mt].x), __float_as_uint(ahi[mt].x),
                                   __float_as_uint(alo[mt].y), __float_as_uint(ahi[mt].y) };
                mma_tf32(acc[mt][nt], a0, b0);
                uint32_t a1[4] = { __float_as_uint(alo[mt].z), __float_as_uint(ahi[mt].z),
                                   __float_as_uint(alo[mt].w), __float_as_uint(ahi[mt].w) };
                mma_tf32(acc[mt][nt], a1, b1);
            }
        }
        __syncthreads();
    }

    // store accums to slab [128][130]
#pragma unroll
    for (int mt = 0; mt < 2; mt++) {
        int r = wm + mt*16 + lr;
#pragma unroll
        for (int nt = 0; nt < 8; nt++) {
            int c = wn + nt*8 + lq*2;
            *(float2*)(slab + (size_t)r*130 + c)     = make_float2(acc[mt][nt][0], acc[mt][nt][1]);
            *(float2*)(slab + (size_t)(r+8)*130 + c) = make_float2(acc[mt][nt][2], acc[mt][nt][3]);
        }
    }
    __syncthreads();

    const int col = tid & 127, seg = tid >> 7;
    {
        float m = -INFINITY; int ri = 0;
        for (int r = seg*64; r < seg*64 + 64; r++) {
            float v = slab[(size_t)r*130 + col];
            if (v > m) { m = v; ri = r; }
        }
        redm[seg][col] = m; redi[seg][col] = ri;
    }
    __syncthreads();
    if (tid < 128) {
        float m = redm[0][tid]; int ri = redi[0][tid];
        float v = redm[1][tid];
        if (v > m) { m = v; ri = redi[1][tid]; }
        colmax_s[tid] = m;
        long pi = ((long)k*RBLK + rb)*BB + n0 + tid;
        g_pm[pi] = m; g_pidx[pi] = m0 + ri;
        int tr = (T_INc + k)*BB + n0 + tid - m0;
        if (tr >= 0 && tr < 128)
            g_diag[k*BB + n0 + tid] = slab[(size_t)tr*130 + tid];
    }
    __syncthreads();
    {
        float cm = colmax_s[col], s = 0.f;
        for (int r = seg*64; r < seg*64 + 64; r++)
            s += fexp(slab[(size_t)r*130 + col] - cm);
        reds[seg][col] = s;
    }
    __syncthreads();
    if (tid < 128) {
        long pi = ((long)k*RBLK + rb)*BB + n0 + tid;
        g_ps[pi] = reds[0][tid] + reds[1][tid];
    }
}

// ---------------------------------------------------------------- combine / finalize
__global__ void combine_kernel() {
    const int k = blockIdx.x, c = threadIdx.x;
    const float* pm = g_pm + (long)k*RBLK*BB;
    const int*  pid = g_pidx + (long)k*RBLK*BB;
    const float* ps = g_ps + (long)k*RBLK*BB;
    float m = pm[c]; int idx = pid[c];
    for (int rb = 1; rb < RBLK; rb++) {
        float v = pm[(long)rb*BB + c];
        if (v > m) { m = v; idx = pid[(long)rb*BB + c]; }
    }
    float s = 0.f;
    for (int rb = 0; rb < RBLK; rb++)
        s += ps[(long)rb*BB + c] * fexp(pm[(long)rb*BB + c] - m);
    float lse = m + logf(s);
    g_dll[k*BB + c] = g_diag[k*BB + c] - lse;
    g_corr[k*BB + c] = (idx == BB*(T_INc + k) + c) ? 1 : 0;
}

__global__ void finalize_kernel(float* __restrict__ out) {
    __shared__ float ssum[256];
    __shared__ int scnt[256];
    const int tid = threadIdx.x;
    float s = 0.f; int cnt = 0;
    for (int i = tid; i < T_OUTc*BB; i += 256) { s += g_dll[i]; cnt += g_corr[i]; }
    ssum[tid] = s; scnt[tid] = cnt;
    __syncthreads();
    for (int o = 128; o > 0; o >>= 1) {
        if (tid < o) { ssum[tid] += ssum[tid+o]; scnt[tid] += scnt[tid+o]; }
        __syncthreads();
    }
    if (tid == 0) {
        out[0] = (float)scnt[0] / (float)(T_OUTc*BB);
        out[1] = -ssum[0] / (float)(T_OUTc*BB);
    }
}

extern "C" void kernel_launch(void* const* d_in, const int* in_sizes, int n_in,
                              void* d_out, int out_size) {
    const float* X      = (const float*)d_in[0];
    const float* conv_w = (const float*)d_in[1];
    const float* conv_b = (const float*)d_in[2];
    const float* W_ih   = (const float*)d_in[3];
    const float* W_hh   = (const float*)d_in[4];
    const float* b_ih   = (const float*)d_in[5];
    const float* b_hh   = (const float*)d_in[6];
    const float* pred_W = (const float*)d_in[7];
    const float* pred_b = (const float*)d_in[8];
    float* out = (float*)d_out;

    float* enc_p; cudaGetSymbolAddress((void**)&enc_p, g_enc);
    float* gi_p;  cudaGetSymbolAddress((void**)&gi_p,  g_gi);
    float* h_p;   cudaGetSymbolAddress((void**)&h_p,   g_h);
    float* Q_p;   cudaGetSymbolAddress((void**)&Q_p,   g_Q);

    const int SIM_SMEM = 128*130*4;   // 66560 B (slab ⊇ 16KB staging)
    cudaFuncSetAttribute(sim_mma_kernel,
                         cudaFuncAttributeMaxDynamicSharedMemorySize, SIM_SMEM);

    conv_kernel<<<dim3(7,256), 256>>>(X, conv_w, conv_b);
    gemm_bias_kernel<<<dim3(256,6,1), 256>>>(enc_p, W_ih, b_ih, gi_p, 0,0,0,0, 768);
    gru_kernel<<<128, 512>>>(W_hh, b_hh, out);
    gemm_bias_kernel<<<dim3(2,2,12), 256>>>(h_p, pred_W, pred_b, Q_p,
                                            0, LAT*LAT, LAT, BB*LAT, LAT);
    sim_mma_kernel<<<dim3(RBLK, 2, T_OUTc), 256, SIM_SMEM>>>();
    combine_kernel<<<T_OUTc, 256>>>();
    finalize_kernel<<<1, 256>>>(out);
}

// round 15
// speedup vs baseline: 1.0851x; 1.0256x over previous
#include <cuda_runtime.h>
#include <cuda_fp16.h>
#include <math.h>
#include <stdint.h>

#define T_INc  128
#define T_OUTc 12
#define LAT    256
#define SQ     140
#define BB     256
#define NROWS  (SQ*BB)      // 35840
#define RBLK   280          // 35840/128

__device__ float g_enc[SQ*BB*LAT];
__device__ float g_gi [T_INc*BB*3*LAT];
__device__ float g_Q  [T_OUTc*BB*LAT];
__device__ float g_h  [BB*LAT];
__device__ float g_pm [T_OUTc*RBLK*BB];
__device__ float g_ps [T_OUTc*RBLK*BB];
__device__ int   g_pidx[T_OUTc*RBLK*BB];
__device__ float g_diag[T_OUTc*BB];
__device__ float g_dll [T_OUTc*BB];
__device__ int   g_corr[T_OUTc*BB];

typedef unsigned long long u64;

#define FMA2(d, a, b) \
    asm("fma.rn.f32x2 %0, %1, %2, %0;" : "+l"(d) : "l"(a), "l"(b))
#define PACK2(out, lo, hi) \
    asm("mov.b64 %0, {%1, %2};" : "=l"(out) : "f"(lo), "f"(hi))
#define UNPACK2(lo, hi, in) \
    asm("mov.b64 {%0, %1}, %2;" : "=f"(lo), "=f"(hi) : "l"(in))

__device__ __forceinline__ uint32_t f2h2(float x, float y) {
    __half2 h = __floats2half2_rn(x, y);
    return *(uint32_t*)&h;
}

__device__ __forceinline__ void mma_f16(float d[4],
                                        uint32_t a0, uint32_t a1, uint32_t a2, uint32_t a3,
                                        uint32_t b0, uint32_t b1) {
    asm volatile(
        "mma.sync.aligned.m16n8k16.row.col.f32.f16.f16.f32 "
        "{%0,%1,%2,%3}, {%4,%5,%6,%7}, {%8,%9}, {%0,%1,%2,%3};"
        : "+f"(d[0]), "+f"(d[1]), "+f"(d[2]), "+f"(d[3])
        : "r"(a0), "r"(a1), "r"(a2), "r"(a3), "r"(b0), "r"(b1));
}

// MUFU-free exp for x <= 0 (clamped at -80)
__device__ __forceinline__ float fexp(float x) {
    x = fmaxf(x, -80.f);
    float y = x * 1.4426950408889634f;
    float r = rintf(y);
    float f = y - r;
    float p = 1.3333558e-3f;
    p = fmaf(p, f, 9.6181291e-3f);
    p = fmaf(p, f, 5.5504110e-2f);
    p = fmaf(p, f, 2.4022651e-1f);
    p = fmaf(p, f, 6.9314718e-1f);
    p = fmaf(p, f, 1.0f);
    int i = (int)r;
    return __uint_as_float(__float_as_uint(p) + ((uint32_t)i << 23));
}

// ---------------------------------------------------------------- conv
__global__ void conv_kernel(const float* __restrict__ X,
                            const float* __restrict__ W,
                            const float* __restrict__ bias) {
    __shared__ float Xs[960];
    const int b = blockIdx.y, t0 = blockIdx.x*20, o = threadIdx.x;
    float w[48];
#pragma unroll
    for (int i = 0; i < 48; i++) w[i] = W[o*48+i];
    const float bb = bias[o];
    const float* xp = X + ((long)b*2048 + (long)t0*4)*12;
    for (int i = threadIdx.x; i < 960; i += 256) Xs[i] = xp[i];
    __syncthreads();
    for (int tt = 0; tt < 20; tt++) {
        float acc = bb;
#pragma unroll
        for (int s = 0; s < 4; s++)
#pragma unroll
            for (int c = 0; c < 12; c++)
                acc += Xs[(tt*4+s)*12+c] * w[c*4+s];
        g_enc[((long)(t0+tt)*BB + b)*LAT + o] = acc;
    }
}

// ------------------------------------------------- packed-f32x2 fp32 GEMM (GI, Q)
__device__ __forceinline__ void gemm_tile2(const float* __restrict__ A,
                                           const float* __restrict__ Bm,
                                           int m0, int n0,
                                           u64 acc2[8][4],
                                           float As[16][128], float Bs[16][128]) {
    const int tid = threadIdx.x, tx = tid & 15, ty = tid >> 4;
#pragma unroll
    for (int r = 0; r < 8; r++)
#pragma unroll
        for (int p = 0; p < 4; p++) acc2[r][p] = 0ull;
    for (int kt = 0; kt < 256; kt += 16) {
#pragma unroll
        for (int i = 0; i < 2; i++) {
            int v = tid*2+i, row = v>>2, kk = (v&3)*4;
            float4 a = *(const float4*)(A + (long)(m0+row)*256 + kt + kk);
            As[kk+0][row]=a.x; As[kk+1][row]=a.y; As[kk+2][row]=a.z; As[kk+3][row]=a.w;
            float4 bq = *(const float4*)(Bm + (long)(n0+row)*256 + kt + kk);
            Bs[kk+0][row]=bq.x; Bs[kk+1][row]=bq.y; Bs[kk+2][row]=bq.z; Bs[kk+3][row]=bq.w;
        }
        __syncthreads();
#pragma unroll
        for (int kk = 0; kk < 16; kk++) {
            float a[8];
            *(float4*)(a)   = *(const float4*)&As[kk][ty*4];
            *(float4*)(a+4) = *(const float4*)&As[kk][64+ty*4];
            float4 b0 = *(const float4*)&Bs[kk][tx*4];
            float4 b1 = *(const float4*)&Bs[kk][64+tx*4];
            u64 bp[4];
            PACK2(bp[0], b0.x, b0.y); PACK2(bp[1], b0.z, b0.w);
            PACK2(bp[2], b1.x, b1.y); PACK2(bp[3], b1.z, b1.w);
#pragma unroll
            for (int r = 0; r < 8; r++) {
                u64 av; PACK2(av, a[r], a[r]);
#pragma unroll
                for (int p = 0; p < 4; p++) FMA2(acc2[r][p], av, bp[p]);
            }
        }
        __syncthreads();
    }
}

__device__ __forceinline__ void unpack_acc(const u64 acc2[8][4], float acc[8][8]) {
#pragma unroll
    for (int r = 0; r < 8; r++) {
        UNPACK2(acc[r][0], acc[r][1], acc2[r][0]);
        UNPACK2(acc[r][2], acc[r][3], acc2[r][1]);
        UNPACK2(acc[r][4], acc[r][5], acc2[r][2]);
        UNPACK2(acc[r][6], acc[r][7], acc2[r][3]);
    }
}

__global__ void gemm_bias_kernel(const float* __restrict__ A,
                                 const float* __restrict__ Bm,
                                 const float* __restrict__ bias,
                                 float* __restrict__ C,
                                 int ldA_batch, int ldB_batch, int ldbias_batch,
                                 int ldC_batch, int ncols) {
    __shared__ float As[16][128], Bs[16][128];
    u64 acc2[8][4];
    float acc[8][8];
    const int k = blockIdx.z;
    const int m0 = blockIdx.x*128, n0 = blockIdx.y*128;
    gemm_tile2(A + (long)k*ldA_batch, Bm + (long)k*ldB_batch, m0, n0, acc2, As, Bs);
    unpack_acc(acc2, acc);
    const float* bk = bias + (long)k*ldbias_batch;
    float* Ck = C + (long)k*ldC_batch;
    const int tx = threadIdx.x & 15, ty = threadIdx.x >> 4;
#pragma unroll
    for (int r = 0; r < 8; r++) {
        int grow = m0 + ((r<4) ? ty*4+r : 64+ty*4+(r-4));
#pragma unroll
        for (int h = 0; h < 2; h++) {
            int gc = n0 + (h?64:0) + tx*4;
            float4 v;
            v.x = acc[r][h*4+0]+bk[gc+0]; v.y = acc[r][h*4+1]+bk[gc+1];
            v.z = acc[r][h*4+2]+bk[gc+2]; v.w = acc[r][h*4+3]+bk[gc+3];
            *(float4*)(Ck + (long)grow*ncols + gc) = v;
        }
    }
}

// ---------------------------------------------------------------- GRU (128 CTAs x 2 chains)
__global__ void gru_kernel(const float* __restrict__ Whh,
                           const float* __restrict__ bhh,
                           float* __restrict__ out) {
    __shared__ float h_s[2][256];
    __shared__ float part[3][2][256];
    const int tid = threadIdx.x, hid = tid & 255, ks = tid >> 8;
    const int b0 = blockIdx.x * 2;
    for (int i = tid; i < 512; i += 512) ((float*)h_s)[i] = 0.f;
    float bh0=0.f, bh1=0.f, bh2=0.f;
    if (ks == 0) { bh0 = bhh[hid]; bh1 = bhh[256+hid]; bh2 = bhh[512+hid]; }
    __syncthreads();
    const float* W0 = Whh + (long)hid*256;
    const float* W1 = Whh + (long)(256+hid)*256;
    const float* W2 = Whh + (long)(512+hid)*256;
    const int kbase = ks * 128;
    for (int t = 0; t < T_INc; t++) {
        float a0[2]={0,0}, a1[2]={0,0}, a2[2]={0,0};
#pragma unroll 4
        for (int k = kbase; k < kbase+128; k += 4) {
            float4 w0 = *(const float4*)(W0+k);
            float4 w1 = *(const float4*)(W1+k);
            float4 w2 = *(const float4*)(W2+k);
#pragma unroll
            for (int bl = 0; bl < 2; bl++) {
                float4 hv = *(const float4*)&h_s[bl][k];
                a0[bl] += w0.x*hv.x + w0.y*hv.y + w0.z*hv.z + w0.w*hv.w;
                a1[bl] += w1.x*hv.x + w1.y*hv.y + w1.z*hv.z + w1.w*hv.w;
                a2[bl] += w2.x*hv.x + w2.y*hv.y + w2.z*hv.z + w2.w*hv.w;
            }
        }
        if (ks == 1) {
#pragma unroll
            for (int bl = 0; bl < 2; bl++) {
                part[0][bl][hid]=a0[bl]; part[1][bl][hid]=a1[bl]; part[2][bl][hid]=a2[bl];
            }
        }
        __syncthreads();
        if (ks == 0) {
            const float* gi = g_gi + ((long)t*BB + b0)*768;
#pragma unroll
            for (int bl = 0; bl < 2; bl++) {
                float ghr = a0[bl]+part[0][bl][hid]+bh0;
                float ghz = a1[bl]+part[1][bl][hid]+bh1;
                float ghn = a2[bl]+part[2][bl][hid]+bh2;
                float gr = gi[(long)bl*768 + hid]     + ghr;
                float gz = gi[(long)bl*768 + 256+hid] + ghz;
                float gn = gi[(long)bl*768 + 512+hid];
                float r = 1.f/(1.f+expf(-gr));
                float z = 1.f/(1.f+expf(-gz));
                float n = tanhf(gn + r*ghn);
                h_s[bl][hid] = (1.f-z)*n + z*h_s[bl][hid];
            }
        }
        __syncthreads();
    }
    if (ks == 0) {
#pragma unroll
        for (int bl = 0; bl < 2; bl++) {
            int b = b0+bl;
            float hv = h_s[bl][hid];
            g_h[b*256+hid] = hv;
            out[2 + b*256 + hid] = hv;
        }
    }
}

// --------------------------------------- sim: f16 mma k16, R7 loop structure
// CTA 128x128xK256; 8 warps (4m x 2n). k16 chunks = 1 mma-K each.
// Staging: AsH/BsH [128 rows][10 u32] (40B stride), k-pair-permuted so one
// LDS.64 per fragment returns (k-lo, k-hi). Permutation applied to A and B
// consistently => product invariant. Epilogue slab reuses staging memory.
__global__ void __launch_bounds__(256) sim_mma_kernel() {
    extern __shared__ float dsm[];
    uint32_t* AsH = (uint32_t*)dsm;          // [128*10]
    uint32_t* BsH = AsH + 1280;              // [128*10]
    float* slab = dsm;                        // [128][130] epilogue

    __shared__ float redm[2][128], reds[2][128], colmax_s[128];
    __shared__ int   redi[2][128];

    const int tid = threadIdx.x, lane = tid & 31, warp = tid >> 5;
    const int wm = (warp & 3) * 32;
    const int wn = (warp >> 2) * 64;
    const int lq = lane & 3, lr = lane >> 2;
    const int rb = blockIdx.x, cb = blockIdx.y, k = blockIdx.z;
    const int m0 = rb*128, n0 = cb*128;
    const float* Ag = g_enc + (size_t)m0*256;
    const float* Bg = g_Q + (size_t)k*BB*LAT + (size_t)n0*256;

    float acc[2][8][4];
#pragma unroll
    for (int mt = 0; mt < 2; mt++)
#pragma unroll
        for (int nt = 0; nt < 8; nt++)
#pragma unroll
            for (int i = 0; i < 4; i++) acc[mt][nt][i] = 0.f;

    for (int kt = 0; kt < 256; kt += 16) {
#pragma unroll
        for (int s = 0; s < 2; s++) {
            int v = tid*2 + s;
            int m = v >> 2, j = v & 3;
            int pos0 = (j & 1)*4 + (j >> 1);           // pair 2j
            float4 av = *(const float4*)(Ag + (size_t)m*256 + kt + j*4);
            AsH[m*10 + pos0]     = f2h2(av.x, av.y);
            AsH[m*10 + pos0 + 2] = f2h2(av.z, av.w);   // pair 2j+1
            float4 bv = *(const float4*)(Bg + (size_t)m*256 + kt + j*4);
            BsH[m*10 + pos0]     = f2h2(bv.x, bv.y);
            BsH[m*10 + pos0 + 2] = f2h2(bv.z, bv.w);
        }
        __syncthreads();

        uint2 alo[2], ahi[2];
#pragma unroll
        for (int mt = 0; mt < 2; mt++) {
            int mrow = wm + mt*16 + lr;
            alo[mt] = *(const uint2*)(AsH + mrow*10 + lq*2);        // (a0, a2)
            ahi[mt] = *(const uint2*)(AsH + (mrow+8)*10 + lq*2);    // (a1, a3)
        }
#pragma unroll
        for (int nt = 0; nt < 8; nt++) {
            int nrow = wn + nt*8 + lr;
            uint2 bh = *(const uint2*)(BsH + nrow*10 + lq*2);       // (b0, b1)
#pragma unroll
            for (int mt = 0; mt < 2; mt++) {
                mma_f16(acc[mt][nt], alo[mt].x, ahi[mt].x,
                                      alo[mt].y, ahi[mt].y, bh.x, bh.y);
            }
        }
        __syncthreads();
    }

    // store accums to slab [128][130]
#pragma unroll
    for (int mt = 0; mt < 2; mt++) {
        int r = wm + mt*16 + lr;
#pragma unroll
        for (int nt = 0; nt < 8; nt++) {
            int c = wn + nt*8 + lq*2;
            *(float2*)(slab + (size_t)r*130 + c)     = make_float2(acc[mt][nt][0], acc[mt][nt][1]);
            *(float2*)(slab + (size_t)(r+8)*130 + c) = make_float2(acc[mt][nt][2], acc[mt][nt][3]);
        }
    }
    __syncthreads();

    const int col = tid & 127, seg = tid >> 7;
    {
        float m = -INFINITY; int ri = 0;
        for (int r = seg*64; r < seg*64 + 64; r++) {
            float v = slab[(size_t)r*130 + col];
            if (v > m) { m = v; ri = r; }
        }
        redm[seg][col] = m; redi[seg][col] = ri;
    }
    __syncthreads();
    if (tid < 128) {
        float m = redm[0][tid]; int ri = redi[0][tid];
        float v = redm[1][tid];
        if (v > m) { m = v; ri = redi[1][tid]; }
        colmax_s[tid] = m;
        long pi = ((long)k*RBLK + rb)*BB + n0 + tid;
        g_pm[pi] = m; g_pidx[pi] = m0 + ri;
        int tr = (T_INc + k)*BB + n0 + tid - m0;
        if (tr >= 0 && tr < 128)
            g_diag[k*BB + n0 + tid] = slab[(size_t)tr*130 + tid];
    }
    __syncthreads();
    {
        float cm = colmax_s[col], s = 0.f;
        for (int r = seg*64; r < seg*64 + 64; r++)
            s += fexp(slab[(size_t)r*130 + col] - cm);
        reds[seg][col] = s;
    }
    __syncthreads();
    if (tid < 128) {
        long pi = ((long)k*RBLK + rb)*BB + n0 + tid;
        g_ps[pi] = reds[0][tid] + reds[1][tid];
    }
}

// ---------------------------------------------------------------- combine / finalize
__global__ void combine_kernel() {
    const int k = blockIdx.x, c = threadIdx.x;
    const float* pm = g_pm + (long)k*RBLK*BB;
    const int*  pid = g_pidx + (long)k*RBLK*BB;
    const float* ps = g_ps + (long)k*RBLK*BB;
    float m = pm[c]; int idx = pid[c];
    for (int rb = 1; rb < RBLK; rb++) {
        float v = pm[(long)rb*BB + c];
        if (v > m) { m = v; idx = pid[(long)rb*BB + c]; }
    }
    float s = 0.f;
    for (int rb = 0; rb < RBLK; rb++)
        s += ps[(long)rb*BB + c] * fexp(pm[(long)rb*BB + c] - m);
    float lse = m + logf(s);
    g_dll[k*BB + c] = g_diag[k*BB + c] - lse;
    g_corr[k*BB + c] = (idx == BB*(T_INc + k) + c) ? 1 : 0;
}

__global__ void finalize_kernel(float* __restrict__ out) {
    __shared__ float ssum[256];
    __shared__ int scnt[256];
    const int tid = threadIdx.x;
    float s = 0.f; int cnt = 0;
    for (int i = tid; i < T_OUTc*BB; i += 256) { s += g_dll[i]; cnt += g_corr[i]; }
    ssum[tid] = s; scnt[tid] = cnt;
    __syncthreads();
    for (int o = 128; o > 0; o >>= 1) {
        if (tid < o) { ssum[tid] += ssum[tid+o]; scnt[tid] += scnt[tid+o]; }
        __syncthreads();
    }
    if (tid == 0) {
        out[0] = (float)scnt[0] / (float)(T_OUTc*BB);
        out[1] = -ssum[0] / (float)(T_OUTc*BB);
    }
}

extern "C" void kernel_launch(void* const* d_in, const int* in_sizes, int n_in,
                              void* d_out, int out_size) {
    const float* X      = (const float*)d_in[0];
    const float* conv_w = (const float*)d_in[1];
    const float* conv_b = (const float*)d_in[2];
    const float* W_ih   = (const float*)d_in[3];
    const float* W_hh   = (const float*)d_in[4];
    const float* b_ih   = (const float*)d_in[5];
    const float* b_hh   = (const float*)d_in[6];
    const float* pred_W = (const float*)d_in[7];
    const float* pred_b = (const float*)d_in[8];
    float* out = (float*)d_out;

    float* enc_p; cudaGetSymbolAddress((void**)&enc_p, g_enc);
    float* gi_p;  cudaGetSymbolAddress((void**)&gi_p,  g_gi);
    float* h_p;   cudaGetSymbolAddress((void**)&h_p,   g_h);
    float* Q_p;   cudaGetSymbolAddress((void**)&Q_p,   g_Q);

    const int SIM_SMEM = 128*130*4;   // 66560 B (slab ⊇ 10KB f16 staging)
    cudaFuncSetAttribute(sim_mma_kernel,
                         cudaFuncAttributeMaxDynamicSharedMemorySize, SIM_SMEM);

    conv_kernel<<<dim3(7,256), 256>>>(X, conv_w, conv_b);
    gemm_bias_kernel<<<dim3(256,6,1), 256>>>(enc_p, W_ih, b_ih, gi_p, 0,0,0,0, 768);
    gru_kernel<<<128, 512>>>(W_hh, b_hh, out);
    gemm_bias_kernel<<<dim3(2,2,12), 256>>>(h_p, pred_W, pred_b, Q_p,
                                            0, LAT*LAT, LAT, BB*LAT, LAT);
    sim_mma_kernel<<<dim3(RBLK, 2, T_OUTc), 256, SIM_SMEM>>>();
    combine_kernel<<<T_OUTc, 256>>>();
    finalize_kernel<<<1, 256>>>(out);
}

// round 16
// speedup vs baseline: 1.0931x; 1.0074x over previous
#include <cuda_runtime.h>
#include <cuda_fp16.h>
#include <math.h>
#include <stdint.h>

#define T_INc  128
#define T_OUTc 12
#define LAT    256
#define SQ     140
#define BB     256
#define NROWS  (SQ*BB)      // 35840
#define RBLK   280          // 35840/128

__device__ float g_enc[SQ*BB*LAT];
__device__ float g_gi [T_INc*BB*3*LAT];
__device__ float g_Q  [T_OUTc*BB*LAT];
__device__ float g_h  [BB*LAT];
__device__ float g_pm [T_OUTc*RBLK*BB];
__device__ float g_ps [T_OUTc*RBLK*BB];
__device__ int   g_pidx[T_OUTc*RBLK*BB];
__device__ float g_diag[T_OUTc*BB];
__device__ float g_dll [T_OUTc*BB];
__device__ int   g_corr[T_OUTc*BB];

typedef unsigned long long u64;

#define FMA2(d, a, b) \
    asm("fma.rn.f32x2 %0, %1, %2, %0;" : "+l"(d) : "l"(a), "l"(b))
#define PACK2(out, lo, hi) \
    asm("mov.b64 %0, {%1, %2};" : "=l"(out) : "f"(lo), "f"(hi))
#define UNPACK2(lo, hi, in) \
    asm("mov.b64 {%0, %1}, %2;" : "=f"(lo), "=f"(hi) : "l"(in))

__device__ __forceinline__ uint32_t f2h2(float x, float y) {
    __half2 h = __floats2half2_rn(x, y);
    return *(uint32_t*)&h;
}

__device__ __forceinline__ void mma_f16(float d[4],
                                        uint32_t a0, uint32_t a1, uint32_t a2, uint32_t a3,
                                        uint32_t b0, uint32_t b1) {
    asm volatile(
        "mma.sync.aligned.m16n8k16.row.col.f32.f16.f16.f32 "
        "{%0,%1,%2,%3}, {%4,%5,%6,%7}, {%8,%9}, {%0,%1,%2,%3};"
        : "+f"(d[0]), "+f"(d[1]), "+f"(d[2]), "+f"(d[3])
        : "r"(a0), "r"(a1), "r"(a2), "r"(a3), "r"(b0), "r"(b1));
}

// MUFU-free exp for x <= 0 (clamped at -80)
__device__ __forceinline__ float fexp(float x) {
    x = fmaxf(x, -80.f);
    float y = x * 1.4426950408889634f;
    float r = rintf(y);
    float f = y - r;
    float p = 1.3333558e-3f;
    p = fmaf(p, f, 9.6181291e-3f);
    p = fmaf(p, f, 5.5504110e-2f);
    p = fmaf(p, f, 2.4022651e-1f);
    p = fmaf(p, f, 6.9314718e-1f);
    p = fmaf(p, f, 1.0f);
    int i = (int)r;
    return __uint_as_float(__float_as_uint(p) + ((uint32_t)i << 23));
}

// ---------------------------------------------------------------- conv
__global__ void conv_kernel(const float* __restrict__ X,
                            const float* __restrict__ W,
                            const float* __restrict__ bias) {
    __shared__ float Xs[960];
    const int b = blockIdx.y, t0 = blockIdx.x*20, o = threadIdx.x;
    float w[48];
#pragma unroll
    for (int i = 0; i < 48; i++) w[i] = W[o*48+i];
    const float bb = bias[o];
    const float* xp = X + ((long)b*2048 + (long)t0*4)*12;
    for (int i = threadIdx.x; i < 960; i += 256) Xs[i] = xp[i];
    __syncthreads();
    for (int tt = 0; tt < 20; tt++) {
        float acc = bb;
#pragma unroll
        for (int s = 0; s < 4; s++)
#pragma unroll
            for (int c = 0; c < 12; c++)
                acc += Xs[(tt*4+s)*12+c] * w[c*4+s];
        g_enc[((long)(t0+tt)*BB + b)*LAT + o] = acc;
    }
}

// ------------------------------------------------- packed-f32x2 fp32 GEMM (GI, Q)
__device__ __forceinline__ void gemm_tile2(const float* __restrict__ A,
                                           const float* __restrict__ Bm,
                                           int m0, int n0,
                                           u64 acc2[8][4],
                                           float As[16][128], float Bs[16][128]) {
    const int tid = threadIdx.x, tx = tid & 15, ty = tid >> 4;
#pragma unroll
    for (int r = 0; r < 8; r++)
#pragma unroll
        for (int p = 0; p < 4; p++) acc2[r][p] = 0ull;
    for (int kt = 0; kt < 256; kt += 16) {
#pragma unroll
        for (int i = 0; i < 2; i++) {
            int v = tid*2+i, row = v>>2, kk = (v&3)*4;
            float4 a = *(const float4*)(A + (long)(m0+row)*256 + kt + kk);
            As[kk+0][row]=a.x; As[kk+1][row]=a.y; As[kk+2][row]=a.z; As[kk+3][row]=a.w;
            float4 bq = *(const float4*)(Bm + (long)(n0+row)*256 + kt + kk);
            Bs[kk+0][row]=bq.x; Bs[kk+1][row]=bq.y; Bs[kk+2][row]=bq.z; Bs[kk+3][row]=bq.w;
        }
        __syncthreads();
#pragma unroll
        for (int kk = 0; kk < 16; kk++) {
            float a[8];
            *(float4*)(a)   = *(const float4*)&As[kk][ty*4];
            *(float4*)(a+4) = *(const float4*)&As[kk][64+ty*4];
            float4 b0 = *(const float4*)&Bs[kk][tx*4];
            float4 b1 = *(const float4*)&Bs[kk][64+tx*4];
            u64 bp[4];
            PACK2(bp[0], b0.x, b0.y); PACK2(bp[1], b0.z, b0.w);
            PACK2(bp[2], b1.x, b1.y); PACK2(bp[3], b1.z, b1.w);
#pragma unroll
            for (int r = 0; r < 8; r++) {
                u64 av; PACK2(av, a[r], a[r]);
#pragma unroll
                for (int p = 0; p < 4; p++) FMA2(acc2[r][p], av, bp[p]);
            }
        }
        __syncthreads();
    }
}

__device__ __forceinline__ void unpack_acc(const u64 acc2[8][4], float acc[8][8]) {
#pragma unroll
    for (int r = 0; r < 8; r++) {
        UNPACK2(acc[r][0], acc[r][1], acc2[r][0]);
        UNPACK2(acc[r][2], acc[r][3], acc2[r][1]);
        UNPACK2(acc[r][4], acc[r][5], acc2[r][2]);
        UNPACK2(acc[r][6], acc[r][7], acc2[r][3]);
    }
}

__global__ void gemm_bias_kernel(const float* __restrict__ A,
                                 const float* __restrict__ Bm,
                                 const float* __restrict__ bias,
                                 float* __restrict__ C,
                                 int ldA_batch, int ldB_batch, int ldbias_batch,
                                 int ldC_batch, int ncols) {
    __shared__ float As[16][128], Bs[16][128];
    u64 acc2[8][4];
    float acc[8][8];
    const int k = blockIdx.z;
    const int m0 = blockIdx.x*128, n0 = blockIdx.y*128;
    gemm_tile2(A + (long)k*ldA_batch, Bm + (long)k*ldB_batch, m0, n0, acc2, As, Bs);
    unpack_acc(acc2, acc);
    const float* bk = bias + (long)k*ldbias_batch;
    float* Ck = C + (long)k*ldC_batch;
    const int tx = threadIdx.x & 15, ty = threadIdx.x >> 4;
#pragma unroll
    for (int r = 0; r < 8; r++) {
        int grow = m0 + ((r<4) ? ty*4+r : 64+ty*4+(r-4));
#pragma unroll
        for (int h = 0; h < 2; h++) {
            int gc = n0 + (h?64:0) + tx*4;
            float4 v;
            v.x = acc[r][h*4+0]+bk[gc+0]; v.y = acc[r][h*4+1]+bk[gc+1];
            v.z = acc[r][h*4+2]+bk[gc+2]; v.w = acc[r][h*4+3]+bk[gc+3];
            *(float4*)(Ck + (long)grow*ncols + gc) = v;
        }
    }
}

// ---------------------------------------------------------------- GRU (128 CTAs x 2 chains)
__global__ void gru_kernel(const float* __restrict__ Whh,
                           const float* __restrict__ bhh,
                           float* __restrict__ out) {
    __shared__ float h_s[2][256];
    __shared__ float part[3][2][256];
    const int tid = threadIdx.x, hid = tid & 255, ks = tid >> 8;
    const int b0 = blockIdx.x * 2;
    for (int i = tid; i < 512; i += 512) ((float*)h_s)[i] = 0.f;
    float bh0=0.f, bh1=0.f, bh2=0.f;
    if (ks == 0) { bh0 = bhh[hid]; bh1 = bhh[256+hid]; bh2 = bhh[512+hid]; }
    __syncthreads();
    const float* W0 = Whh + (long)hid*256;
    const float* W1 = Whh + (long)(256+hid)*256;
    const float* W2 = Whh + (long)(512+hid)*256;
    const int kbase = ks * 128;
    for (int t = 0; t < T_INc; t++) {
        float a0[2]={0,0}, a1[2]={0,0}, a2[2]={0,0};
#pragma unroll 4
        for (int k = kbase; k < kbase+128; k += 4) {
            float4 w0 = *(const float4*)(W0+k);
            float4 w1 = *(const float4*)(W1+k);
            float4 w2 = *(const float4*)(W2+k);
#pragma unroll
            for (int bl = 0; bl < 2; bl++) {
                float4 hv = *(const float4*)&h_s[bl][k];
                a0[bl] += w0.x*hv.x + w0.y*hv.y + w0.z*hv.z + w0.w*hv.w;
                a1[bl] += w1.x*hv.x + w1.y*hv.y + w1.z*hv.z + w1.w*hv.w;
                a2[bl] += w2.x*hv.x + w2.y*hv.y + w2.z*hv.z + w2.w*hv.w;
            }
        }
        if (ks == 1) {
#pragma unroll
            for (int bl = 0; bl < 2; bl++) {
                part[0][bl][hid]=a0[bl]; part[1][bl][hid]=a1[bl]; part[2][bl][hid]=a2[bl];
            }
        }
        __syncthreads();
        if (ks == 0) {
            const float* gi = g_gi + ((long)t*BB + b0)*768;
#pragma unroll
            for (int bl = 0; bl < 2; bl++) {
                float ghr = a0[bl]+part[0][bl][hid]+bh0;
                float ghz = a1[bl]+part[1][bl][hid]+bh1;
                float ghn = a2[bl]+part[2][bl][hid]+bh2;
                float gr = gi[(long)bl*768 + hid]     + ghr;
                float gz = gi[(long)bl*768 + 256+hid] + ghz;
                float gn = gi[(long)bl*768 + 512+hid];
                float r = 1.f/(1.f+expf(-gr));
                float z = 1.f/(1.f+expf(-gz));
                float n = tanhf(gn + r*ghn);
                h_s[bl][hid] = (1.f-z)*n + z*h_s[bl][hid];
            }
        }
        __syncthreads();
    }
    if (ks == 0) {
#pragma unroll
        for (int bl = 0; bl < 2; bl++) {
            int b = b0+bl;
            float hv = h_s[bl][hid];
            g_h[b*256+hid] = hv;
            out[2 + b*256 + hid] = hv;
        }
    }
}

// --------------------------------------- sim: f16 mma k16, N=256 CTA tile
// CTA 128x256xK256; 8 warps (4m x 2n), warp tile 32x128 (nt=16).
// Staging: AsH [128][10] u32, BsH [256][10] u32, k-pair permuted (LDS.64/frag).
// Epilogue: two 128-col halves through the [128][130] slab.
__global__ void __launch_bounds__(256, 1) sim_mma_kernel() {
    extern __shared__ float dsm[];
    uint32_t* AsH = (uint32_t*)dsm;          // [128*10]
    uint32_t* BsH = AsH + 1280;              // [256*10]
    float* slab = dsm;                        // [128][130] epilogue

    __shared__ float redm[2][128], reds[2][128], colmax_s[128];
    __shared__ int   redi[2][128];

    const int tid = threadIdx.x, lane = tid & 31, warp = tid >> 5;
    const int wm = (warp & 3) * 32;
    const int wn = (warp >> 2) * 128;
    const int lq = lane & 3, lr = lane >> 2;
    const int rb = blockIdx.x, k = blockIdx.y;
    const int m0 = rb*128;
    const float* Ag = g_enc + (size_t)m0*256;
    const float* Bg = g_Q + (size_t)k*BB*LAT;

    float acc[2][16][4];
#pragma unroll
    for (int mt = 0; mt < 2; mt++)
#pragma unroll
        for (int nt = 0; nt < 16; nt++)
#pragma unroll
            for (int i = 0; i < 4; i++) acc[mt][nt][i] = 0.f;

    for (int kt = 0; kt < 256; kt += 16) {
        // stage A (512 float4 slots) + B (1024 slots): 6 per thread
#pragma unroll
        for (int s = 0; s < 6; s++) {
            int v = tid + s*256;
            if (v < 512) {
                int m = v >> 2, j = v & 3;
                int pos0 = (j & 1)*4 + (j >> 1);
                float4 av = *(const float4*)(Ag + (size_t)m*256 + kt + j*4);
                AsH[m*10 + pos0]     = f2h2(av.x, av.y);
                AsH[m*10 + pos0 + 2] = f2h2(av.z, av.w);
            } else {
                int vb = v - 512;
                int m = vb >> 2, j = vb & 3;
                int pos0 = (j & 1)*4 + (j >> 1);
                float4 bv = *(const float4*)(Bg + (size_t)m*256 + kt + j*4);
                BsH[m*10 + pos0]     = f2h2(bv.x, bv.y);
                BsH[m*10 + pos0 + 2] = f2h2(bv.z, bv.w);
            }
        }
        __syncthreads();

        uint2 alo[2], ahi[2];
#pragma unroll
        for (int mt = 0; mt < 2; mt++) {
            int mrow = wm + mt*16 + lr;
            alo[mt] = *(const uint2*)(AsH + mrow*10 + lq*2);
            ahi[mt] = *(const uint2*)(AsH + (mrow+8)*10 + lq*2);
        }
#pragma unroll
        for (int nt = 0; nt < 16; nt++) {
            int nrow = wn + nt*8 + lr;
            uint2 bh = *(const uint2*)(BsH + nrow*10 + lq*2);
#pragma unroll
            for (int mt = 0; mt < 2; mt++) {
                mma_f16(acc[mt][nt], alo[mt].x, ahi[mt].x,
                                      alo[mt].y, ahi[mt].y, bh.x, bh.y);
            }
        }
        __syncthreads();
    }

    // epilogue: two 128-column halves
    for (int hh = 0; hh < 2; hh++) {
        const int n0 = hh*128;
        // store this half's accums into slab
#pragma unroll
        for (int mt = 0; mt < 2; mt++) {
            int r = wm + mt*16 + lr;
#pragma unroll
            for (int nt = 0; nt < 16; nt++) {
                int cg = wn + nt*8 + lq*2;
                if ((cg >> 7) == hh) {
                    int c = cg & 127;
                    *(float2*)(slab + (size_t)r*130 + c)     = make_float2(acc[mt][nt][0], acc[mt][nt][1]);
                    *(float2*)(slab + (size_t)(r+8)*130 + c) = make_float2(acc[mt][nt][2], acc[mt][nt][3]);
                }
            }
        }
        __syncthreads();

        const int col = tid & 127, seg = tid >> 7;
        {
            float m = -INFINITY; int ri = 0;
            for (int r = seg*64; r < seg*64 + 64; r++) {
                float v = slab[(size_t)r*130 + col];
                if (v > m) { m = v; ri = r; }
            }
            redm[seg][col] = m; redi[seg][col] = ri;
        }
        __syncthreads();
        if (tid < 128) {
            float m = redm[0][tid]; int ri = redi[0][tid];
            float v = redm[1][tid];
            if (v > m) { m = v; ri = redi[1][tid]; }
            colmax_s[tid] = m;
            long pi = ((long)k*RBLK + rb)*BB + n0 + tid;
            g_pm[pi] = m; g_pidx[pi] = m0 + ri;
            int tr = (T_INc + k)*BB + n0 + tid - m0;
            if (tr >= 0 && tr < 128)
                g_diag[k*BB + n0 + tid] = slab[(size_t)tr*130 + tid];
        }
        __syncthreads();
        {
            float cm = colmax_s[col], s = 0.f;
            for (int r = seg*64; r < seg*64 + 64; r++)
                s += fexp(slab[(size_t)r*130 + col] - cm);
            reds[seg][col] = s;
        }
        __syncthreads();
        if (tid < 128) {
            long pi = ((long)k*RBLK + rb)*BB + n0 + tid;
            g_ps[pi] = reds[0][tid] + reds[1][tid];
        }
        __syncthreads();
    }
}

// ---------------------------------------------------------------- combine / finalize
__global__ void combine_kernel() {
    const int k = blockIdx.x, c = threadIdx.x;
    const float* pm = g_pm + (long)k*RBLK*BB;
    const int*  pid = g_pidx + (long)k*RBLK*BB;
    const float* ps = g_ps + (long)k*RBLK*BB;
    float m = pm[c]; int idx = pid[c];
    for (int rb = 1; rb < RBLK; rb++) {
        float v = pm[(long)rb*BB + c];
        if (v > m) { m = v; idx = pid[(long)rb*BB + c]; }
    }
    float s = 0.f;
    for (int rb = 0; rb < RBLK; rb++)
        s += ps[(long)rb*BB + c] * fexp(pm[(long)rb*BB + c] - m);
    float lse = m + logf(s);
    g_dll[k*BB + c] = g_diag[k*BB + c] - lse;
    g_corr[k*BB + c] = (idx == BB*(T_INc + k) + c) ? 1 : 0;
}

__global__ void finalize_kernel(float* __restrict__ out) {
    __shared__ float ssum[256];
    __shared__ int scnt[256];
    const int tid = threadIdx.x;
    float s = 0.f; int cnt = 0;
    for (int i = tid; i < T_OUTc*BB; i += 256) { s += g_dll[i]; cnt += g_corr[i]; }
    ssum[tid] = s; scnt[tid] = cnt;
    __syncthreads();
    for (int o = 128; o > 0; o >>= 1) {
        if (tid < o) { ssum[tid] += ssum[tid+o]; scnt[tid] += scnt[tid+o]; }
        __syncthreads();
    }
    if (tid == 0) {
        out[0] = (float)scnt[0] / (float)(T_OUTc*BB);
        out[1] = -ssum[0] / (float)(T_OUTc*BB);
    }
}

extern "C" void kernel_launch(void* const* d_in, const int* in_sizes, int n_in,
                              void* d_out, int out_size) {
    const float* X      = (const float*)d_in[0];
    const float* conv_w = (const float*)d_in[1];
    const float* conv_b = (const float*)d_in[2];
    const float* W_ih   = (const float*)d_in[3];
    const float* W_hh   = (const float*)d_in[4];
    const float* b_ih   = (const float*)d_in[5];
    const float* b_hh   = (const float*)d_in[6];
    const float* pred_W = (const float*)d_in[7];
    const float* pred_b = (const float*)d_in[8];
    float* out = (float*)d_out;

    float* enc_p; cudaGetSymbolAddress((void**)&enc_p, g_enc);
    float* gi_p;  cudaGetSymbolAddress((void**)&gi_p,  g_gi);
    float* h_p;   cudaGetSymbolAddress((void**)&h_p,   g_h);
    float* Q_p;   cudaGetSymbolAddress((void**)&Q_p,   g_Q);

    const int SIM_SMEM = 128*130*4;   // 66560 B (slab ⊇ 15.4KB f16 staging)
    cudaFuncSetAttribute(sim_mma_kernel,
                         cudaFuncAttributeMaxDynamicSharedMemorySize, SIM_SMEM);

    conv_kernel<<<dim3(7,256), 256>>>(X, conv_w, conv_b);
    gemm_bias_kernel<<<dim3(256,6,1), 256>>>(enc_p, W_ih, b_ih, gi_p, 0,0,0,0, 768);
    gru_kernel<<<128, 512>>>(W_hh, b_hh, out);
    gemm_bias_kernel<<<dim3(2,2,12), 256>>>(h_p, pred_W, pred_b, Q_p,
                                            0, LAT*LAT, LAT, BB*LAT, LAT);
    sim_mma_kernel<<<dim3(RBLK, T_OUTc), 256, SIM_SMEM>>>();
    combine_kernel<<<T_OUTc, 256>>>();
    finalize_kernel<<<1, 256>>>(out);
}

// round 17
// speedup vs baseline: 1.9184x; 1.7550x over previous
#include <cuda_runtime.h>
#include <cuda_fp16.h>
#include <math.h>
#include <stdint.h>

#define T_INc  128
#define T_OUTc 12
#define LAT    256
#define SQ     140
#define BB     256
#define NROWS  (SQ*BB)      // 35840
#define RBLK   280          // 35840/128

__device__ float g_enc[SQ*BB*LAT];
__device__ float g_gi [T_INc*BB*3*LAT];
__device__ float g_Q  [T_OUTc*BB*LAT];
__device__ float g_h  [BB*LAT];
__device__ float g_pm [T_OUTc*RBLK*BB];
__device__ float g_ps [T_OUTc*RBLK*BB];
__device__ int   g_pidx[T_OUTc*RBLK*BB];
__device__ float g_diag[T_OUTc*BB];
__device__ float g_dll [T_OUTc*BB];
__device__ int   g_corr[T_OUTc*BB];
__device__ float g_hT[2][LAT*BB];      // h transposed [k][b], ping-pong
__device__ unsigned g_sync;

typedef unsigned long long u64;

#define FMA2(d, a, b) \
    asm("fma.rn.f32x2 %0, %1, %2, %0;" : "+l"(d) : "l"(a), "l"(b))
#define PACK2(out, lo, hi) \
    asm("mov.b64 %0, {%1, %2};" : "=l"(out) : "f"(lo), "f"(hi))
#define UNPACK2(lo, hi, in) \
    asm("mov.b64 {%0, %1}, %2;" : "=f"(lo), "=f"(hi) : "l"(in))

__device__ __forceinline__ uint32_t f2h2(float x, float y) {
    __half2 h = __floats2half2_rn(x, y);
    return *(uint32_t*)&h;
}

__device__ __forceinline__ void mma_f16(float d[4],
                                        uint32_t a0, uint32_t a1, uint32_t a2, uint32_t a3,
                                        uint32_t b0, uint32_t b1) {
    asm volatile(
        "mma.sync.aligned.m16n8k16.row.col.f32.f16.f16.f32 "
        "{%0,%1,%2,%3}, {%4,%5,%6,%7}, {%8,%9}, {%0,%1,%2,%3};"
        : "+f"(d[0]), "+f"(d[1]), "+f"(d[2]), "+f"(d[3])
        : "r"(a0), "r"(a1), "r"(a2), "r"(a3), "r"(b0), "r"(b1));
}

// MUFU-free exp for x <= 0 (clamped at -80)
__device__ __forceinline__ float fexp(float x) {
    x = fmaxf(x, -80.f);
    float y = x * 1.4426950408889634f;
    float r = rintf(y);
    float f = y - r;
    float p = 1.3333558e-3f;
    p = fmaf(p, f, 9.6181291e-3f);
    p = fmaf(p, f, 5.5504110e-2f);
    p = fmaf(p, f, 2.4022651e-1f);
    p = fmaf(p, f, 6.9314718e-1f);
    p = fmaf(p, f, 1.0f);
    int i = (int)r;
    return __uint_as_float(__float_as_uint(p) + ((uint32_t)i << 23));
}

// ---------------------------------------------------------------- conv
__global__ void conv_kernel(const float* __restrict__ X,
                            const float* __restrict__ W,
                            const float* __restrict__ bias) {
    __shared__ float Xs[960];
    const int b = blockIdx.y, t0 = blockIdx.x*20, o = threadIdx.x;
    float w[48];
#pragma unroll
    for (int i = 0; i < 48; i++) w[i] = W[o*48+i];
    const float bb = bias[o];
    const float* xp = X + ((long)b*2048 + (long)t0*4)*12;
    for (int i = threadIdx.x; i < 960; i += 256) Xs[i] = xp[i];
    __syncthreads();
    for (int tt = 0; tt < 20; tt++) {
        float acc = bb;
#pragma unroll
        for (int s = 0; s < 4; s++)
#pragma unroll
            for (int c = 0; c < 12; c++)
                acc += Xs[(tt*4+s)*12+c] * w[c*4+s];
        g_enc[((long)(t0+tt)*BB + b)*LAT + o] = acc;
    }
}

// ------------------------------------------------- packed-f32x2 fp32 GEMM (GI, Q)
__device__ __forceinline__ void gemm_tile2(const float* __restrict__ A,
                                           const float* __restrict__ Bm,
                                           int m0, int n0,
                                           u64 acc2[8][4],
                                           float As[16][128], float Bs[16][128]) {
    const int tid = threadIdx.x, tx = tid & 15, ty = tid >> 4;
#pragma unroll
    for (int r = 0; r < 8; r++)
#pragma unroll
        for (int p = 0; p < 4; p++) acc2[r][p] = 0ull;
    for (int kt = 0; kt < 256; kt += 16) {
#pragma unroll
        for (int i = 0; i < 2; i++) {
            int v = tid*2+i, row = v>>2, kk = (v&3)*4;
            float4 a = *(const float4*)(A + (long)(m0+row)*256 + kt + kk);
            As[kk+0][row]=a.x; As[kk+1][row]=a.y; As[kk+2][row]=a.z; As[kk+3][row]=a.w;
            float4 bq = *(const float4*)(Bm + (long)(n0+row)*256 + kt + kk);
            Bs[kk+0][row]=bq.x; Bs[kk+1][row]=bq.y; Bs[kk+2][row]=bq.z; Bs[kk+3][row]=bq.w;
        }
        __syncthreads();
#pragma unroll
        for (int kk = 0; kk < 16; kk++) {
            float a[8];
            *(float4*)(a)   = *(const float4*)&As[kk][ty*4];
            *(float4*)(a+4) = *(const float4*)&As[kk][64+ty*4];
            float4 b0 = *(const float4*)&Bs[kk][tx*4];
            float4 b1 = *(const float4*)&Bs[kk][64+tx*4];
            u64 bp[4];
            PACK2(bp[0], b0.x, b0.y); PACK2(bp[1], b0.z, b0.w);
            PACK2(bp[2], b1.x, b1.y); PACK2(bp[3], b1.z, b1.w);
#pragma unroll
            for (int r = 0; r < 8; r++) {
                u64 av; PACK2(av, a[r], a[r]);
#pragma unroll
                for (int p = 0; p < 4; p++) FMA2(acc2[r][p], av, bp[p]);
            }
        }
        __syncthreads();
    }
}

__device__ __forceinline__ void unpack_acc(const u64 acc2[8][4], float acc[8][8]) {
#pragma unroll
    for (int r = 0; r < 8; r++) {
        UNPACK2(acc[r][0], acc[r][1], acc2[r][0]);
        UNPACK2(acc[r][2], acc[r][3], acc2[r][1]);
        UNPACK2(acc[r][4], acc[r][5], acc2[r][2]);
        UNPACK2(acc[r][6], acc[r][7], acc2[r][3]);
    }
}

__global__ void gemm_bias_kernel(const float* __restrict__ A,
                                 const float* __restrict__ Bm,
                                 const float* __restrict__ bias,
                                 float* __restrict__ C,
                                 int ldA_batch, int ldB_batch, int ldbias_batch,
                                 int ldC_batch, int ncols) {
    __shared__ float As[16][128], Bs[16][128];
    u64 acc2[8][4];
    float acc[8][8];
    const int k = blockIdx.z;
    const int m0 = blockIdx.x*128, n0 = blockIdx.y*128;
    gemm_tile2(A + (long)k*ldA_batch, Bm + (long)k*ldB_batch, m0, n0, acc2, As, Bs);
    unpack_acc(acc2, acc);
    const float* bk = bias + (long)k*ldbias_batch;
    float* Ck = C + (long)k*ldC_batch;
    const int tx = threadIdx.x & 15, ty = threadIdx.x >> 4;
#pragma unroll
    for (int r = 0; r < 8; r++) {
        int grow = m0 + ((r<4) ? ty*4+r : 64+ty*4+(r-4));
#pragma unroll
        for (int h = 0; h < 2; h++) {
            int gc = n0 + (h?64:0) + tx*4;
            float4 v;
            v.x = acc[r][h*4+0]+bk[gc+0]; v.y = acc[r][h*4+1]+bk[gc+1];
            v.z = acc[r][h*4+2]+bk[gc+2]; v.w = acc[r][h*4+3]+bk[gc+3];
            *(float4*)(Ck + (long)grow*ncols + gc) = v;
        }
    }
}

// ---------------------------------------------------------------- persistent GRU
// 128 CTAs, CTA i owns hid {2i, 2i+1} for ALL batches. W rows (6KB) in smem,
// h ping-pong in g_hT [k][b] (coalesced). Grid-wide spin sync each step.
__global__ void gru_init_kernel() { g_sync = 0u; }

__global__ void __launch_bounds__(512, 1) gru_pers_kernel(
        const float* __restrict__ Whh,
        const float* __restrict__ bhh,
        float* __restrict__ out) {
    __shared__ float Ws[6][256];
    __shared__ float part[6][256];
    const int tid = threadIdx.x;
    const int b  = tid & 255;
    const int kh = tid >> 8;
    const int hid0 = blockIdx.x*2, hid1 = hid0 + 1;

    // load 6 W rows: j = g*2 + hl, row = g*256 + hid0 + hl
    for (int i = tid; i < 6*256; i += 512) {
        int j = i >> 8, kk = i & 255;
        int g = j >> 1, hl = j & 1;
        Ws[j][kk] = Whh[(size_t)(g*256 + hid0 + hl)*256 + kk];
    }
    float h0 = 0.f, h1 = 0.f;
    float bh0r=0,bh1r=0,bh0z=0,bh1z=0,bh0n=0,bh1n=0;
    if (kh == 0) {
        bh0r = bhh[hid0];       bh1r = bhh[hid1];
        bh0z = bhh[256 + hid0]; bh1z = bhh[256 + hid1];
        bh0n = bhh[512 + hid0]; bh1n = bhh[512 + hid1];
    }
    __syncthreads();

    for (int t = 0; t < T_INc; t++) {
        float a[6] = {0,0,0,0,0,0};
        if (t > 0) {
            const float* hp = g_hT[t & 1] + kh*128*256 + b;
            const float* w0 = &Ws[0][kh*128];
            const float* w1 = &Ws[1][kh*128];
            const float* w2 = &Ws[2][kh*128];
            const float* w3 = &Ws[3][kh*128];
            const float* w4 = &Ws[4][kh*128];
            const float* w5 = &Ws[5][kh*128];
#pragma unroll 4
            for (int k = 0; k < 128; k++) {
                float hv = hp[(size_t)k*256];
                a[0] = fmaf(hv, w0[k], a[0]);
                a[1] = fmaf(hv, w1[k], a[1]);
                a[2] = fmaf(hv, w2[k], a[2]);
                a[3] = fmaf(hv, w3[k], a[3]);
                a[4] = fmaf(hv, w4[k], a[4]);
                a[5] = fmaf(hv, w5[k], a[5]);
            }
        }
        if (kh == 1) {
#pragma unroll
            for (int j = 0; j < 6; j++) part[j][b] = a[j];
        }
        __syncthreads();
        if (kh == 0) {
            const float* gi = g_gi + ((size_t)t*BB + b)*768;
            float ghr0 = a[0] + part[0][b] + bh0r;
            float ghr1 = a[1] + part[1][b] + bh1r;
            float ghz0 = a[2] + part[2][b] + bh0z;
            float ghz1 = a[3] + part[3][b] + bh1z;
            float ghn0 = a[4] + part[4][b] + bh0n;
            float ghn1 = a[5] + part[5][b] + bh1n;
            float r0 = 1.f/(1.f + expf(-(gi[hid0] + ghr0)));
            float r1 = 1.f/(1.f + expf(-(gi[hid1] + ghr1)));
            float z0 = 1.f/(1.f + expf(-(gi[256+hid0] + ghz0)));
            float z1 = 1.f/(1.f + expf(-(gi[256+hid1] + ghz1)));
            float n0 = tanhf(gi[512+hid0] + r0*ghn0);
            float n1 = tanhf(gi[512+hid1] + r1*ghn1);
            h0 = (1.f - z0)*n0 + z0*h0;
            h1 = (1.f - z1)*n1 + z1*h1;
            float* dst = g_hT[(t+1) & 1];
            dst[(size_t)hid0*256 + b] = h0;
            dst[(size_t)hid1*256 + b] = h1;
        }
        __threadfence();
        __syncthreads();
        if (tid == 0) {
            atomicAdd(&g_sync, 1u);
            unsigned target = (unsigned)(t+1) * gridDim.x;
            unsigned v;
            do {
                asm volatile("ld.global.acquire.gpu.u32 %0, [%1];"
                             : "=r"(v) : "l"(&g_sync));
                if (v < target) __nanosleep(64);
            } while (v < target);
        }
        __syncthreads();
    }
    if (kh == 0) {
        g_h[b*256 + hid0] = h0;
        g_h[b*256 + hid1] = h1;
        out[2 + b*256 + hid0] = h0;
        out[2 + b*256 + hid1] = h1;
    }
}

// --------------------------------------- sim: f16 mma k16, N=256 CTA tile (R16)
__global__ void __launch_bounds__(256, 1) sim_mma_kernel() {
    extern __shared__ float dsm[];
    uint32_t* AsH = (uint32_t*)dsm;          // [128*10]
    uint32_t* BsH = AsH + 1280;              // [256*10]
    float* slab = dsm;                        // [128][130] epilogue

    __shared__ float redm[2][128], reds[2][128], colmax_s[128];
    __shared__ int   redi[2][128];

    const int tid = threadIdx.x, lane = tid & 31, warp = tid >> 5;
    const int wm = (warp & 3) * 32;
    const int wn = (warp >> 2) * 128;
    const int lq = lane & 3, lr = lane >> 2;
    const int rb = blockIdx.x, k = blockIdx.y;
    const int m0 = rb*128;
    const float* Ag = g_enc + (size_t)m0*256;
    const float* Bg = g_Q + (size_t)k*BB*LAT;

    float acc[2][16][4];
#pragma unroll
    for (int mt = 0; mt < 2; mt++)
#pragma unroll
        for (int nt = 0; nt < 16; nt++)
#pragma unroll
            for (int i = 0; i < 4; i++) acc[mt][nt][i] = 0.f;

    for (int kt = 0; kt < 256; kt += 16) {
#pragma unroll
        for (int s = 0; s < 6; s++) {
            int v = tid + s*256;
            if (v < 512) {
                int m = v >> 2, j = v & 3;
                int pos0 = (j & 1)*4 + (j >> 1);
                float4 av = *(const float4*)(Ag + (size_t)m*256 + kt + j*4);
                AsH[m*10 + pos0]     = f2h2(av.x, av.y);
                AsH[m*10 + pos0 + 2] = f2h2(av.z, av.w);
            } else {
                int vb = v - 512;
                int m = vb >> 2, j = vb & 3;
                int pos0 = (j & 1)*4 + (j >> 1);
                float4 bv = *(const float4*)(Bg + (size_t)m*256 + kt + j*4);
                BsH[m*10 + pos0]     = f2h2(bv.x, bv.y);
                BsH[m*10 + pos0 + 2] = f2h2(bv.z, bv.w);
            }
        }
        __syncthreads();

        uint2 alo[2], ahi[2];
#pragma unroll
        for (int mt = 0; mt < 2; mt++) {
            int mrow = wm + mt*16 + lr;
            alo[mt] = *(const uint2*)(AsH + mrow*10 + lq*2);
            ahi[mt] = *(const uint2*)(AsH + (mrow+8)*10 + lq*2);
        }
#pragma unroll
        for (int nt = 0; nt < 16; nt++) {
            int nrow = wn + nt*8 + lr;
            uint2 bh = *(const uint2*)(BsH + nrow*10 + lq*2);
#pragma unroll
            for (int mt = 0; mt < 2; mt++) {
                mma_f16(acc[mt][nt], alo[mt].x, ahi[mt].x,
                                      alo[mt].y, ahi[mt].y, bh.x, bh.y);
            }
        }
        __syncthreads();
    }

    for (int hh = 0; hh < 2; hh++) {
        const int n0 = hh*128;
#pragma unroll
        for (int mt = 0; mt < 2; mt++) {
            int r = wm + mt*16 + lr;
#pragma unroll
            for (int nt = 0; nt < 16; nt++) {
                int cg = wn + nt*8 + lq*2;
                if ((cg >> 7) == hh) {
                    int c = cg & 127;
                    *(float2*)(slab + (size_t)r*130 + c)     = make_float2(acc[mt][nt][0], acc[mt][nt][1]);
                    *(float2*)(slab + (size_t)(r+8)*130 + c) = make_float2(acc[mt][nt][2], acc[mt][nt][3]);
                }
            }
        }
        __syncthreads();

        const int col = tid & 127, seg = tid >> 7;
        {
            float m = -INFINITY; int ri = 0;
            for (int r = seg*64; r < seg*64 + 64; r++) {
                float v = slab[(size_t)r*130 + col];
                if (v > m) { m = v; ri = r; }
            }
            redm[seg][col] = m; redi[seg][col] = ri;
        }
        __syncthreads();
        if (tid < 128) {
            float m = redm[0][tid]; int ri = redi[0][tid];
            float v = redm[1][tid];
            if (v > m) { m = v; ri = redi[1][tid]; }
            colmax_s[tid] = m;
            long pi = ((long)k*RBLK + rb)*BB + n0 + tid;
            g_pm[pi] = m; g_pidx[pi] = m0 + ri;
            int tr = (T_INc + k)*BB + n0 + tid - m0;
            if (tr >= 0 && tr < 128)
                g_diag[k*BB + n0 + tid] = slab[(size_t)tr*130 + tid];
        }
        __syncthreads();
        {
            float cm = colmax_s[col], s = 0.f;
            for (int r = seg*64; r < seg*64 + 64; r++)
                s += fexp(slab[(size_t)r*130 + col] - cm);
            reds[seg][col] = s;
        }
        __syncthreads();
        if (tid < 128) {
            long pi = ((long)k*RBLK + rb)*BB + n0 + tid;
            g_ps[pi] = reds[0][tid] + reds[1][tid];
        }
        __syncthreads();
    }
}

// ---------------------------------------------------------------- combine / finalize
__global__ void combine_kernel() {
    const int k = blockIdx.x, c = threadIdx.x;
    const float* pm = g_pm + (long)k*RBLK*BB;
    const int*  pid = g_pidx + (long)k*RBLK*BB;
    const float* ps = g_ps + (long)k*RBLK*BB;
    float m = pm[c]; int idx = pid[c];
    for (int rb = 1; rb < RBLK; rb++) {
        float v = pm[(long)rb*BB + c];
        if (v > m) { m = v; idx = pid[(long)rb*BB + c]; }
    }
    float s = 0.f;
    for (int rb = 0; rb < RBLK; rb++)
        s += ps[(long)rb*BB + c] * fexp(pm[(long)rb*BB + c] - m);
    float lse = m + logf(s);
    g_dll[k*BB + c] = g_diag[k*BB + c] - lse;
    g_corr[k*BB + c] = (idx == BB*(T_INc + k) + c) ? 1 : 0;
}

__global__ void finalize_kernel(float* __restrict__ out) {
    __shared__ float ssum[256];
    __shared__ int scnt[256];
    const int tid = threadIdx.x;
    float s = 0.f; int cnt = 0;
    for (int i = tid; i < T_OUTc*BB; i += 256) { s += g_dll[i]; cnt += g_corr[i]; }
    ssum[tid] = s; scnt[tid] = cnt;
    __syncthreads();
    for (int o = 128; o > 0; o >>= 1) {
        if (tid < o) { ssum[tid] += ssum[tid+o]; scnt[tid] += scnt[tid+o]; }
        __syncthreads();
    }
    if (tid == 0) {
        out[0] = (float)scnt[0] / (float)(T_OUTc*BB);
        out[1] = -ssum[0] / (float)(T_OUTc*BB);
    }
}

extern "C" void kernel_launch(void* const* d_in, const int* in_sizes, int n_in,
                              void* d_out, int out_size) {
    const float* X      = (const float*)d_in[0];
    const float* conv_w = (const float*)d_in[1];
    const float* conv_b = (const float*)d_in[2];
    const float* W_ih   = (const float*)d_in[3];
    const float* W_hh   = (const float*)d_in[4];
    const float* b_ih   = (const float*)d_in[5];
    const float* b_hh   = (const float*)d_in[6];
    const float* pred_W = (const float*)d_in[7];
    const float* pred_b = (const float*)d_in[8];
    float* out = (float*)d_out;

    float* enc_p; cudaGetSymbolAddress((void**)&enc_p, g_enc);
    float* gi_p;  cudaGetSymbolAddress((void**)&gi_p,  g_gi);
    float* h_p;   cudaGetSymbolAddress((void**)&h_p,   g_h);
    float* Q_p;   cudaGetSymbolAddress((void**)&Q_p,   g_Q);

    const int SIM_SMEM = 128*130*4;   // 66560 B (slab ⊇ 15.4KB f16 staging)
    cudaFuncSetAttribute(sim_mma_kernel,
                         cudaFuncAttributeMaxDynamicSharedMemorySize, SIM_SMEM);

    conv_kernel<<<dim3(7,256), 256>>>(X, conv_w, conv_b);
    gemm_bias_kernel<<<dim3(256,6,1), 256>>>(enc_p, W_ih, b_ih, gi_p, 0,0,0,0, 768);
    gru_init_kernel<<<1, 1>>>();
    gru_pers_kernel<<<128, 512>>>(W_hh, b_hh, out);
    gemm_bias_kernel<<<dim3(2,2,12), 256>>>(h_p, pred_W, pred_b, Q_p,
                                            0, LAT*LAT, LAT, BB*LAT, LAT);
    sim_mma_kernel<<<dim3(RBLK, T_OUTc), 256, SIM_SMEM>>>();
    combine_kernel<<<T_OUTc, 256>>>();
    finalize_kernel<<<1, 256>>>(out);
}